// round 9
// baseline (speedup 1.0000x reference)
#include <cuda_runtime.h>
#include <math.h>

#define NN    16384
#define E_    131072
#define FF    128
#define LL    9
#define RR    8
#define DOUT  1152
#define KM    1024
#define HID   64
#define DA_   64
#define PI_F  3.14159265358979323846f

// ---------------- scratch (device globals; no runtime allocation) ----------------
__device__ float g_hW[(long)NN*FF];
__device__ float g_upd[(long)NN*DOUT];
__device__ float g_hlocal[(long)NN*DOUT];
__device__ float g_m[NN];
__device__ int   g_cnt[NN];
__device__ int   g_cntrank[NN];
__device__ int   g_off[NN+1];
__device__ int   g_cur[NN];
__device__ int   g_eorder[E_];
__device__ int   g_rank[NN];
__device__ unsigned char g_ismaster[NN];
__device__ int   g_master[KM];
__device__ unsigned char g_adj[(long)KM*KM];
__device__ unsigned char g_arec[(long)KM*KM];
__device__ float g_hm[(long)KM*DOUT];
__device__ float g_posm[KM*3];
__device__ float g_hn[(long)KM*FF];
__device__ float g_q[(long)KM*DA_];
__device__ float g_k[(long)KM*DA_];
__device__ float g_updm[(long)KM*DOUT];
__device__ float g_hhier[(long)KM*DOUT];

// ---------------- zero scratch that must start at 0 ----------------
__global__ void zero_kernel() {
    long i = (long)blockIdx.x * 256 + threadIdx.x;
    if (i < NN) { g_cnt[i] = 0; g_cntrank[i] = 0; }
    if (i < (long)KM*KM) g_adj[i] = 0;
    if (i < (long)KM*DOUT) g_hhier[i] = 0.f;
}

// ---------------- generic fp32 SGEMM, 128x128 tile, BK=8, TM=TN=8 ----------------
// Requires M%128==0, Nc%128==0, Kc%(8*gridDim.z)==0.
// gridDim.z>1 -> split-K, accumulates into C via atomicAdd (C must be zeroed).
__global__ __launch_bounds__(256) void sgemm128(
    const float* __restrict__ A, const float* __restrict__ B,
    float* __restrict__ C, int M, int Nc, int Kc)
{
    __shared__ float As[8][128];
    __shared__ float Bs[8][128];
    const int tid = threadIdx.x;
    const int tx = tid & 15;
    const int ty = tid >> 4;
    const long crow0 = (long)blockIdx.y * 128;
    const long ccol0 = (long)blockIdx.x * 128;
    const int aRow = tid >> 1;
    const int aCol = (tid & 1) << 2;
    const int bRow = tid >> 5;
    const int bCol = (tid & 31) << 2;
    const float* Ag = A + (crow0 + aRow) * (long)Kc + aCol;
    const float* Bg = B + ccol0 + bCol + (long)bRow * Nc;

    const int kchunk = Kc / gridDim.z;
    const int kbeg = blockIdx.z * kchunk;
    const int kend = kbeg + kchunk;

    float acc[8][8];
#pragma unroll
    for (int i = 0; i < 8; i++)
#pragma unroll
        for (int j = 0; j < 8; j++) acc[i][j] = 0.f;

    for (int k0 = kbeg; k0 < kend; k0 += 8) {
        float4 a4 = *(const float4*)(Ag + k0);
        float4 b4 = *(const float4*)(Bg + (long)k0 * Nc);
        As[aCol+0][aRow] = a4.x;
        As[aCol+1][aRow] = a4.y;
        As[aCol+2][aRow] = a4.z;
        As[aCol+3][aRow] = a4.w;
        *(float4*)(&Bs[bRow][bCol]) = b4;
        __syncthreads();
#pragma unroll
        for (int kk = 0; kk < 8; kk++) {
            float ar[8], br[8];
            *(float4*)(ar)   = *(const float4*)(&As[kk][ty*8]);
            *(float4*)(ar+4) = *(const float4*)(&As[kk][ty*8+4]);
            *(float4*)(br)   = *(const float4*)(&Bs[kk][tx*8]);
            *(float4*)(br+4) = *(const float4*)(&Bs[kk][tx*8+4]);
#pragma unroll
            for (int i = 0; i < 8; i++)
#pragma unroll
                for (int j = 0; j < 8; j++)
                    acc[i][j] = fmaf(ar[i], br[j], acc[i][j]);
        }
        __syncthreads();
    }

    if (gridDim.z == 1) {
#pragma unroll
        for (int i = 0; i < 8; i++) {
            long row = crow0 + ty*8 + i;
            float* Cp = C + row * (long)Nc + ccol0 + tx*8;
            *(float4*)(Cp)   = make_float4(acc[i][0], acc[i][1], acc[i][2], acc[i][3]);
            *(float4*)(Cp+4) = make_float4(acc[i][4], acc[i][5], acc[i][6], acc[i][7]);
        }
    } else {
#pragma unroll
        for (int i = 0; i < 8; i++) {
            long row = crow0 + ty*8 + i;
            float* Cp = C + row * (long)Nc + ccol0 + tx*8;
#pragma unroll
            for (int j = 0; j < 8; j++) atomicAdd(&Cp[j], acc[i][j]);
        }
    }
}

// ---------------- CSR build (edges grouped by dst) ----------------
__global__ void count_kernel(const int* __restrict__ eidx) {
    int e = blockIdx.x * 256 + threadIdx.x;
    if (e < E_) atomicAdd(&g_cnt[eidx[E_ + e]], 1);
}

__global__ __launch_bounds__(1024) void scan_counts() {
    __shared__ int ssum[1024];
    int t = threadIdx.x;
    int local[16];
    int s = 0;
#pragma unroll
    for (int k = 0; k < 16; k++) { local[k] = s; s += g_cnt[t*16 + k]; }
    ssum[t] = s;
    __syncthreads();
    for (int off = 1; off < 1024; off <<= 1) {
        int v = (t >= off) ? ssum[t - off] : 0;
        __syncthreads();
        ssum[t] += v;
        __syncthreads();
    }
    int base = (t == 0) ? 0 : ssum[t-1];
#pragma unroll
    for (int k = 0; k < 16; k++) {
        int o = base + local[k];
        g_off[t*16 + k] = o;
        g_cur[t*16 + k] = o;
    }
    if (t == 1023) g_off[NN] = ssum[1023];
}

__global__ void scatter_kernel(const int* __restrict__ eidx) {
    int e = blockIdx.x * 256 + threadIdx.x;
    if (e < E_) {
        int d = eidx[E_ + e];
        int p = atomicAdd(&g_cur[d], 1);
        g_eorder[p] = e;
    }
}

// ---------------- per-node message aggregation: upd[n,l,f] ----------------
__global__ __launch_bounds__(128) void upd_kernel(
    const float* __restrict__ esh, const float* __restrict__ efeat,
    const float* __restrict__ Wrad, const int* __restrict__ eidx)
{
    int n = blockIdx.x;
    int f = threadIdx.x;
    __shared__ float sW[RR*FF];
    __shared__ int sE[256];
    for (int t = f; t < RR*FF; t += 128) sW[t] = Wrad[t];
    int beg = g_off[n], end = g_off[n+1];
    int deg = end - beg;
    for (int t = f; t < deg && t < 256; t += 128) sE[t] = g_eorder[beg + t];
    __syncthreads();
    if (f == 0 && deg > 1 && deg <= 256) {
        // deterministic accumulation order (ascending edge id)
        for (int a = 1; a < deg; a++) {
            int v = sE[a]; int b = a - 1;
            while (b >= 0 && sE[b] > v) { sE[b+1] = sE[b]; b--; }
            sE[b+1] = v;
        }
    }
    __syncthreads();
    float acc[LL];
#pragma unroll
    for (int l = 0; l < LL; l++) acc[l] = 0.f;
    for (int p = 0; p < deg; p++) {
        int e = (deg <= 256) ? sE[p] : g_eorder[beg + p];
        int s = eidx[e];
        float rw = 0.f;
#pragma unroll
        for (int r = 0; r < RR; r++) rw = fmaf(efeat[(long)e*RR + r], sW[r*FF + f], rw);
        float tv = g_hW[(long)s*FF + f] * rw;
#pragma unroll
        for (int l = 0; l < LL; l++) acc[l] = fmaf(esh[(long)e*LL + l], tv, acc[l]);
    }
#pragma unroll
    for (int l = 0; l < LL; l++) g_upd[(long)n*DOUT + l*FF + f] = acc[l];
}

// ---------------- epilogues ----------------
__global__ void add_h_kernel(const float* __restrict__ h) {
    int n = blockIdx.x, f = threadIdx.x;
    g_hlocal[(long)n*DOUT + f] += h[(long)n*FF + f];
}

__global__ void add_hm_kernel() {
    int i = blockIdx.x; int g = blockIdx.y*128 + threadIdx.x;
    g_hhier[(long)i*DOUT + g] += g_hm[(long)i*DOUT + g];
}

// ---------------- mask MLP: m = sigmoid(relu(hs@W1+b1)@W2+b2) ----------------
__global__ __launch_bounds__(64) void mlp_kernel(
    const float* __restrict__ W1, const float* __restrict__ b1,
    const float* __restrict__ W2, const float* __restrict__ b2,
    float* __restrict__ out_m)
{
    int n = blockIdx.x, t = threadIdx.x;
    __shared__ float sh_[FF];
    __shared__ float red[2];
    sh_[t]      = g_hlocal[(long)n*DOUT + t];
    sh_[t + 64] = g_hlocal[(long)n*DOUT + t + 64];
    __syncthreads();
    float a = b1[t];
#pragma unroll 8
    for (int f2 = 0; f2 < FF; f2++) a = fmaf(sh_[f2], W1[f2*HID + t], a);
    a = fmaxf(a, 0.f);
    float v = a * W2[t];
#pragma unroll
    for (int o = 16; o; o >>= 1) v += __shfl_down_sync(0xffffffffu, v, o);
    if ((t & 31) == 0) red[t >> 5] = v;
    __syncthreads();
    if (t == 0) {
        float x = red[0] + red[1] + b2[0];
        float mv = 1.f / (1.f + expf(-x));
        g_m[n] = mv;
        out_m[n] = mv;
    }
}

// ---------------- exact top-K rank: count strictly-greater (tie: lower idx) ----------------
__global__ __launch_bounds__(256) void rank_count_kernel() {
    __shared__ float sm[1024];
    int i = blockIdx.x * 256 + threadIdx.x;
    float mi = g_m[i];
    int jb = blockIdx.y * 1024;
    for (int t = threadIdx.x; t < 1024; t += 256) sm[t] = g_m[jb + t];
    __syncthreads();
    int cnt = 0;
#pragma unroll 8
    for (int jj = 0; jj < 1024; jj++) {
        float mj = sm[jj];
        int j = jb + jj;
        cnt += (mj > mi) || (mj == mi && j < i);
    }
    atomicAdd(&g_cntrank[i], cnt);
}

__global__ void mark_master_kernel() {
    int i = blockIdx.x * 256 + threadIdx.x;
    if (i < NN) g_ismaster[i] = (g_cntrank[i] < KM) ? 1 : 0;
}

__global__ __launch_bounds__(1024) void scan_master(float* __restrict__ out_mi) {
    __shared__ int ssum[1024];
    int t = threadIdx.x;
    int local[16];
    int s = 0;
#pragma unroll
    for (int k = 0; k < 16; k++) { local[k] = s; s += (int)g_ismaster[t*16 + k]; }
    ssum[t] = s;
    __syncthreads();
    for (int off = 1; off < 1024; off <<= 1) {
        int v = (t >= off) ? ssum[t - off] : 0;
        __syncthreads();
        ssum[t] += v;
        __syncthreads();
    }
    int base = (t == 0) ? 0 : ssum[t-1];
#pragma unroll
    for (int k = 0; k < 16; k++) {
        int idx = t*16 + k;
        if (g_ismaster[idx]) {
            int pos = base + local[k];
            g_master[pos] = idx;
            g_rank[idx] = pos;
            out_mi[pos] = (float)idx;
        } else {
            g_rank[idx] = KM;
        }
    }
}

// ---------------- induced adjacency among masters (src->dst) ----------------
__global__ void adj_kernel(const int* __restrict__ eidx) {
    int e = blockIdx.x * 256 + threadIdx.x;
    if (e < E_) {
        int rs = g_rank[eidx[e]];
        int rd = g_rank[eidx[E_ + e]];
        if (rs < KM && rd < KM) g_adj[(long)rs*KM + rd] = 1;
    }
}

// ---------------- gather masters ----------------
__global__ void gather_hm_kernel() {
    int i = blockIdx.x; int g = blockIdx.y*128 + threadIdx.x;
    g_hm[(long)i*DOUT + g] = g_hlocal[(long)g_master[i]*DOUT + g];
}

__global__ void gather_posm_kernel(const float* __restrict__ pos) {
    int t = blockIdx.x * 256 + threadIdx.x;
    if (t < KM*3) {
        int i = t / 3, c = t % 3;
        g_posm[t] = pos[(long)g_master[i]*3 + c];
    }
}

// ---------------- q/k projections ----------------
__global__ __launch_bounds__(64) void qk_kernel(
    const float* __restrict__ Wq, const float* __restrict__ Wk)
{
    int i = blockIdx.x, j = threadIdx.x;
    __shared__ float sh_[FF];
    sh_[j] = g_hm[(long)i*DOUT + j];
    sh_[j + 64] = g_hm[(long)i*DOUT + j + 64];
    __syncthreads();
    float q = 0.f, k = 0.f;
#pragma unroll 8
    for (int f = 0; f < FF; f++) {
        float hv = sh_[f];
        q = fmaf(hv, Wq[f*DA_ + j], q);
        k = fmaf(hv, Wk[f*DA_ + j], k);
    }
    g_q[(long)i*DA_ + j] = q;
    g_k[(long)i*DA_ + j] = k;
}

// ---------------- attention + A_virtual output ----------------
__global__ __launch_bounds__(256) void attn_kernel(float* __restrict__ out_av) {
    __shared__ float sq[16][65];
    __shared__ float sk[16][65];
    int bi = blockIdx.y * 16, bj = blockIdx.x * 16;
    int tid = threadIdx.x;
    for (int t = tid; t < 16*64; t += 256) {
        sq[t >> 6][t & 63] = g_q[(long)(bi + (t >> 6))*DA_ + (t & 63)];
        sk[t >> 6][t & 63] = g_k[(long)(bj + (t >> 6))*DA_ + (t & 63)];
    }
    __syncthreads();
    int ti = tid >> 4, tj = tid & 15;
    float d = 0.f;
#pragma unroll 8
    for (int x = 0; x < DA_; x++) d = fmaf(sq[ti][x], sk[tj][x], d);
    float A = 1.f / (1.f + expf(-d * 0.125f));
    out_av[(long)(bi + ti)*KM + (bj + tj)] = (A > 0.5f) ? A : 0.f;
}

// ---------------- receiver adjacency A_rec = adj_master^T ----------------
__global__ void arec_kernel(const float* __restrict__ av) {
    long idx = (long)blockIdx.x * 256 + threadIdx.x;
    int i = (int)(idx / KM), j = (int)(idx % KM);
    bool b = (i != j) &&
             (g_adj[(long)j*KM + i] || av[(long)i*KM + j] > 0.f || av[(long)j*KM + i] > 0.f);
    g_arec[idx] = b ? 1 : 0;
}

// ---------------- hn = h_m @ W_node_h  (K x 1152 x 128), 8 rows/block ----------------
__global__ __launch_bounds__(128) void gemm_hn_kernel(const float* __restrict__ Wnh) {
    int r0 = blockIdx.x * 8;
    int f = threadIdx.x;
    __shared__ float sA[8][DOUT];
    for (int t = f; t < 8*DOUT; t += 128) {
        int rr = t / DOUT, cc = t % DOUT;
        sA[rr][cc] = g_hm[(long)(r0 + rr)*DOUT + cc];
    }
    __syncthreads();
    float acc[8];
#pragma unroll
    for (int rr = 0; rr < 8; rr++) acc[rr] = 0.f;
    for (int kk = 0; kk < DOUT; kk++) {
        float b = Wnh[kk*FF + f];
#pragma unroll
        for (int rr = 0; rr < 8; rr++) acc[rr] = fmaf(sA[rr][kk], b, acc[rr]);
    }
#pragma unroll
    for (int rr = 0; rr < 8; rr++) g_hn[(long)(r0 + rr)*FF + f] = acc[rr];
}

// ---------------- K x K pair aggregation: upd_m[i,l,f] ----------------
__global__ __launch_bounds__(128) void pair_kernel(const float* __restrict__ Wrh) {
    int i0 = blockIdx.x * 2;
    int f = threadIdx.x;
    __shared__ float sposm[KM*3];
    __shared__ float s_sh[2][128][12];   // 9 used, padded for float4 access
    __shared__ float s_rad[2][128][8];
    __shared__ unsigned char s_a[2][128];
    for (int t = f; t < KM*3; t += 128) sposm[t] = g_posm[t];
    float wf[8];
#pragma unroll
    for (int rn = 0; rn < 8; rn++) wf[rn] = Wrh[rn*FF + f];
    __syncthreads();
    float pix[2], piy[2], piz[2];
#pragma unroll
    for (int ii = 0; ii < 2; ii++) {
        pix[ii] = sposm[(i0+ii)*3 + 0];
        piy[ii] = sposm[(i0+ii)*3 + 1];
        piz[ii] = sposm[(i0+ii)*3 + 2];
    }
    float acc[2][LL];
#pragma unroll
    for (int ii = 0; ii < 2; ii++)
#pragma unroll
        for (int l = 0; l < LL; l++) acc[ii][l] = 0.f;
    const float cb = sqrtf(2.f / 5.f);

    for (int jb = 0; jb < KM; jb += 128) {
        int j = jb + f;
        float pjx = sposm[j*3], pjy = sposm[j*3+1], pjz = sposm[j*3+2];
#pragma unroll
        for (int ii = 0; ii < 2; ii++) {
            unsigned char a = g_arec[(long)(i0+ii)*KM + j];
            s_a[ii][f] = a;
            if (a) {
                float vx = pjx - pix[ii], vy = pjy - piy[ii], vz = pjz - piz[ii];
                float r = sqrtf(vx*vx + vy*vy + vz*vz);
                float inv = 1.f / fmaxf(r, 1e-9f);
                float ux = vx*inv, uy = vy*inv, uz = vz*inv;
                s_sh[ii][f][0] = 1.f;
                s_sh[ii][f][1] = ux;
                s_sh[ii][f][2] = uy;
                s_sh[ii][f][3] = uz;
                s_sh[ii][f][4] = ux*uy;
                s_sh[ii][f][5] = uy*uz;
                s_sh[ii][f][6] = 3.f*uz*uz - 1.f;
                s_sh[ii][f][7] = ux*uz;
                s_sh[ii][f][8] = ux*ux - uy*uy;
#pragma unroll
                for (int rn = 0; rn < 8; rn++)
                    s_rad[ii][f][rn] = cb * sinf((float)(rn+1) * PI_F * r * 0.2f) * inv;
            }
        }
        __syncthreads();
        for (int jj = 0; jj < 128; jj++) {
            int a0 = s_a[0][jj], a1 = s_a[1][jj];
            if (!(a0 | a1)) continue;
            float hnf = g_hn[(long)(jb + jj)*FF + f];
#pragma unroll
            for (int ii = 0; ii < 2; ii++) {
                if ((ii == 0 && a0) || (ii == 1 && a1)) {
                    float4 r0 = *(const float4*)(&s_rad[ii][jj][0]);
                    float4 r1 = *(const float4*)(&s_rad[ii][jj][4]);
                    float rw = 0.f;
                    rw = fmaf(r0.x, wf[0], rw); rw = fmaf(r0.y, wf[1], rw);
                    rw = fmaf(r0.z, wf[2], rw); rw = fmaf(r0.w, wf[3], rw);
                    rw = fmaf(r1.x, wf[4], rw); rw = fmaf(r1.y, wf[5], rw);
                    rw = fmaf(r1.z, wf[6], rw); rw = fmaf(r1.w, wf[7], rw);
                    float tmv = hnf * rw;
                    float4 s0 = *(const float4*)(&s_sh[ii][jj][0]);
                    float4 s1 = *(const float4*)(&s_sh[ii][jj][4]);
                    float  s8 = s_sh[ii][jj][8];
                    acc[ii][0] = fmaf(s0.x, tmv, acc[ii][0]);
                    acc[ii][1] = fmaf(s0.y, tmv, acc[ii][1]);
                    acc[ii][2] = fmaf(s0.z, tmv, acc[ii][2]);
                    acc[ii][3] = fmaf(s0.w, tmv, acc[ii][3]);
                    acc[ii][4] = fmaf(s1.x, tmv, acc[ii][4]);
                    acc[ii][5] = fmaf(s1.y, tmv, acc[ii][5]);
                    acc[ii][6] = fmaf(s1.z, tmv, acc[ii][6]);
                    acc[ii][7] = fmaf(s1.w, tmv, acc[ii][7]);
                    acc[ii][8] = fmaf(s8,   tmv, acc[ii][8]);
                }
            }
        }
        __syncthreads();
    }
#pragma unroll
    for (int ii = 0; ii < 2; ii++)
#pragma unroll
        for (int l = 0; l < LL; l++)
            g_updm[(long)(i0+ii)*DOUT + l*FF + f] = acc[ii][l];
}

// ---------------- final combine ----------------
__global__ __launch_bounds__(128) void final_kernel(float* __restrict__ out) {
    int n = blockIdx.x;
    int g = blockIdx.y * 128 + threadIdx.x;
    long idx = (long)n*DOUT + g;
    float mm = g_m[n];
    float hl = g_hlocal[idx];
    int rk = g_rank[n];
    float he = (rk < KM) ? g_hhier[(long)rk*DOUT + g] : 0.f;
    out[idx] = (1.f - mm) * hl + mm * he;
}

// ---------------- launcher ----------------
extern "C" void kernel_launch(void* const* d_in, const int* in_sizes, int n_in,
                              void* d_out, int out_size)
{
    const float* h     = (const float*)d_in[0];
    const float* pos   = (const float*)d_in[1];
    const float* esh   = (const float*)d_in[2];
    const float* efeat = (const float*)d_in[3];
    const float* Wnl   = (const float*)d_in[4];
    const float* Wrl   = (const float*)d_in[5];
    const float* Wpl   = (const float*)d_in[6];
    const float* W1    = (const float*)d_in[7];
    const float* b1    = (const float*)d_in[8];
    const float* W2    = (const float*)d_in[9];
    const float* b2    = (const float*)d_in[10];
    const float* Wq    = (const float*)d_in[11];
    const float* Wk    = (const float*)d_in[12];
    const float* Wnh   = (const float*)d_in[13];
    const float* Wrh   = (const float*)d_in[14];
    const float* Wph   = (const float*)d_in[15];
    const int*   eidx  = (const int*)d_in[16];
    float* out = (float*)d_out;

    const size_t OFF_AV = (size_t)NN * DOUT;
    const size_t OFF_M  = OFF_AV + (size_t)KM * KM;
    const size_t OFF_MI = OFF_M + (size_t)NN;

    // symbol addresses for the generic GEMM (not a stream op; capture-safe)
    void *p_hW = 0, *p_upd = 0, *p_hlocal = 0, *p_updm = 0, *p_hhier = 0;
    cudaGetSymbolAddress(&p_hW, g_hW);
    cudaGetSymbolAddress(&p_upd, g_upd);
    cudaGetSymbolAddress(&p_hlocal, g_hlocal);
    cudaGetSymbolAddress(&p_updm, g_updm);
    cudaGetSymbolAddress(&p_hhier, g_hhier);

    // 0) zero scratch
    zero_kernel<<<4608, 256>>>();

    // 1) hW = h @ W_node_l   (16384 x 128 x 128)
    sgemm128<<<dim3(1, 128, 1), 256>>>(h, Wnl, (float*)p_hW, NN, FF, FF);

    // 2) CSR build (group edges by dst, deterministic order)
    count_kernel<<<E_/256, 256>>>(eidx);
    scan_counts<<<1, 1024>>>();
    scatter_kernel<<<E_/256, 256>>>(eidx);

    // 3) message aggregation -> g_upd (N, 9*128)
    upd_kernel<<<NN, 128>>>(esh, efeat, Wrl, eidx);

    // 4) h_local = upd @ W_prod_l + pad(h)    (16384 x 1152 x 1152)
    sgemm128<<<dim3(DOUT/128, NN/128, 1), 256>>>((const float*)p_upd, Wpl,
                                                 (float*)p_hlocal, NN, DOUT, DOUT);
    add_h_kernel<<<NN, 128>>>(h);

    // 5) mask MLP -> g_m, out m
    mlp_kernel<<<NN, 64>>>(W1, b1, W2, b2, out + OFF_M);

    // 6) exact top-K via full rank counting
    rank_count_kernel<<<dim3(NN/256, 16), 256>>>();
    mark_master_kernel<<<NN/256, 256>>>();
    scan_master<<<1, 1024>>>(out + OFF_MI);

    // 7) induced adjacency + master gathers
    adj_kernel<<<E_/256, 256>>>(eidx);
    gather_hm_kernel<<<dim3(KM, DOUT/128), 128>>>();
    gather_posm_kernel<<<(KM*3 + 255)/256, 256>>>(pos);

    // 8) virtual attention -> out A_virtual, then A_rec
    qk_kernel<<<KM, 64>>>(Wq, Wk);
    attn_kernel<<<dim3(KM/16, KM/16), 256>>>(out + OFF_AV);
    arec_kernel<<<(KM*KM)/256, 256>>>(out + OFF_AV);

    // 9) hierarchical update over K x K pairs
    gemm_hn_kernel<<<KM/8, 128>>>(Wnh);
    pair_kernel<<<KM/2, 128>>>(Wrh);

    // 10) h_hier = upd_m @ W_prod_h + h_m   (1024 x 1152 x 1152, split-K=4)
    sgemm128<<<dim3(DOUT/128, KM/128, 4), 256>>>((const float*)p_updm, Wph,
                                                 (float*)p_hhier, KM, DOUT, DOUT);
    add_hm_kernel<<<dim3(KM, DOUT/128), 128>>>();

    // 11) combine -> out h_final
    final_kernel<<<dim3(NN, DOUT/128), 128>>>(out);
}

// round 10
// speedup vs baseline: 1.0862x; 1.0862x over previous
#include <cuda_runtime.h>
#include <math.h>

#define NN    16384
#define E_    131072
#define FF    128
#define LL    9
#define RR    8
#define DOUT  1152
#define KM    1024
#define HID   64
#define DA_   64
#define PI_F  3.14159265358979323846f

// ---------------- scratch (device globals; no runtime allocation) ----------------
__device__ float g_hW[(long)NN*FF];
__device__ float g_upd[(long)NN*DOUT];
__device__ float g_hlocal[(long)NN*DOUT];
__device__ float g_m[NN];
__device__ int   g_cnt[NN];
__device__ int   g_cntrank[NN];
__device__ int   g_off[NN+1];
__device__ int   g_cur[NN];
__device__ int   g_eorder[E_];
__device__ int   g_rank[NN];
__device__ unsigned char g_ismaster[NN];
__device__ int   g_master[KM];
__device__ unsigned char g_adj[(long)KM*KM];
__device__ unsigned char g_arec[(long)KM*KM];
__device__ float g_hm[(long)KM*DOUT];
__device__ float g_posm[KM*3];
__device__ float g_hn[(long)KM*FF];
__device__ float g_q[(long)KM*DA_];
__device__ float g_k[(long)KM*DA_];
__device__ float g_updm[(long)KM*DOUT];
__device__ float g_hhier[(long)KM*DOUT];

// ---------------- f32x2 packed helpers ----------------
__device__ __forceinline__ unsigned long long ffma2(
    unsigned long long a, unsigned long long b, unsigned long long c)
{
    unsigned long long d;
    asm("fma.rn.f32x2 %0, %1, %2, %3;" : "=l"(d) : "l"(a), "l"(b), "l"(c));
    return d;
}
__device__ __forceinline__ unsigned long long pack2(float x, float y) {
    unsigned long long r;
    asm("mov.b64 %0, {%1, %2};" : "=l"(r) : "f"(x), "f"(y));
    return r;
}
__device__ __forceinline__ void unpack2(unsigned long long v, float& lo, float& hi) {
    asm("mov.b64 {%0, %1}, %2;" : "=f"(lo), "=f"(hi) : "l"(v));
}

// ---------------- zero scratch that must start at 0 ----------------
__global__ void zero_kernel() {
    long i = (long)blockIdx.x * 256 + threadIdx.x;
    if (i < NN) { g_cnt[i] = 0; g_cntrank[i] = 0; }
    if (i < (long)KM*KM) g_adj[i] = 0;
    if (i < (long)KM*DOUT) g_hhier[i] = 0.f;
}

// ---------------- fp32 SGEMM via packed f32x2, 128x128 tile, BK=8, double-buffered ----
// Requires M%128==0, Nc%128==0, Kc%(8*gridDim.z)==0.
// gridDim.z>1 -> split-K, accumulates into C via atomicAdd (C must be zeroed).
__global__ __launch_bounds__(256, 2) void sgemm2(
    const float* __restrict__ A, const float* __restrict__ B,
    float* __restrict__ C, int M, int Nc, int Kc)
{
    __shared__ unsigned long long As2[2][8][128];  // A values duplicated (lo=hi)
    __shared__ float Bs[2][8][128];
    const int tid = threadIdx.x;
    const int tx = tid & 15;            // column group (owns cols tx*2 + 32k)
    const int ty = tid >> 4;            // row group   (owns rows ty*8 .. ty*8+7)
    const long crow0 = (long)blockIdx.y * 128;
    const long ccol0 = (long)blockIdx.x * 128;
    const int aRow = tid >> 1;          // 0..127
    const int aCol = (tid & 1) << 2;    // 0 or 4
    const int bRow = tid >> 5;          // 0..7
    const int bCol = (tid & 31) << 2;   // 0..124
    const float* Ag = A + (crow0 + aRow) * (long)Kc + aCol;
    const float* Bg = B + ccol0 + bCol + (long)bRow * Nc;

    const int kchunk = Kc / gridDim.z;
    const int kbeg = blockIdx.z * kchunk;
    const int nT = kchunk / 8;

    unsigned long long acc[8][4];
#pragma unroll
    for (int i = 0; i < 8; i++)
#pragma unroll
        for (int k = 0; k < 4; k++) acc[i][k] = 0ull;

    // prologue: load tile 0
    float4 a4 = *(const float4*)(Ag + kbeg);
    float4 b4 = *(const float4*)(Bg + (long)kbeg * Nc);
    As2[0][aCol+0][aRow] = pack2(a4.x, a4.x);
    As2[0][aCol+1][aRow] = pack2(a4.y, a4.y);
    As2[0][aCol+2][aRow] = pack2(a4.z, a4.z);
    As2[0][aCol+3][aRow] = pack2(a4.w, a4.w);
    *(float4*)(&Bs[0][bRow][bCol]) = b4;
    __syncthreads();

    for (int t = 0; t < nT; t++) {
        const int cur = t & 1;
        const int nxt = cur ^ 1;
        if (t + 1 < nT) {
            int k0 = kbeg + (t + 1) * 8;
            a4 = *(const float4*)(Ag + k0);
            b4 = *(const float4*)(Bg + (long)k0 * Nc);
        }
#pragma unroll
        for (int kk = 0; kk < 8; kk++) {
            unsigned long long ar[8], br[4];
#pragma unroll
            for (int i = 0; i < 4; i++) {
                ulonglong2 p = *(const ulonglong2*)(&As2[cur][kk][ty*8 + 2*i]);
                ar[2*i]   = p.x;
                ar[2*i+1] = p.y;
            }
#pragma unroll
            for (int k = 0; k < 4; k++)
                br[k] = *(const unsigned long long*)(&Bs[cur][kk][tx*2 + 32*k]);
#pragma unroll
            for (int i = 0; i < 8; i++)
#pragma unroll
                for (int k = 0; k < 4; k++)
                    acc[i][k] = ffma2(ar[i], br[k], acc[i][k]);
        }
        if (t + 1 < nT) {
            As2[nxt][aCol+0][aRow] = pack2(a4.x, a4.x);
            As2[nxt][aCol+1][aRow] = pack2(a4.y, a4.y);
            As2[nxt][aCol+2][aRow] = pack2(a4.z, a4.z);
            As2[nxt][aCol+3][aRow] = pack2(a4.w, a4.w);
            *(float4*)(&Bs[nxt][bRow][bCol]) = b4;
        }
        __syncthreads();
    }

    if (gridDim.z == 1) {
#pragma unroll
        for (int i = 0; i < 8; i++) {
            long row = crow0 + ty*8 + i;
            float* Cp = C + row * (long)Nc + ccol0;
#pragma unroll
            for (int k = 0; k < 4; k++) {
                float lo, hi;
                unpack2(acc[i][k], lo, hi);
                *(float2*)(&Cp[tx*2 + 32*k]) = make_float2(lo, hi);
            }
        }
    } else {
#pragma unroll
        for (int i = 0; i < 8; i++) {
            long row = crow0 + ty*8 + i;
            float* Cp = C + row * (long)Nc + ccol0;
#pragma unroll
            for (int k = 0; k < 4; k++) {
                float lo, hi;
                unpack2(acc[i][k], lo, hi);
                atomicAdd(&Cp[tx*2 + 32*k], lo);
                atomicAdd(&Cp[tx*2 + 32*k + 1], hi);
            }
        }
    }
}

// ---------------- CSR build (edges grouped by dst) ----------------
__global__ void count_kernel(const int* __restrict__ eidx) {
    int e = blockIdx.x * 256 + threadIdx.x;
    if (e < E_) atomicAdd(&g_cnt[eidx[E_ + e]], 1);
}

__global__ __launch_bounds__(1024) void scan_counts() {
    __shared__ int ssum[1024];
    int t = threadIdx.x;
    int local[16];
    int s = 0;
#pragma unroll
    for (int k = 0; k < 16; k++) { local[k] = s; s += g_cnt[t*16 + k]; }
    ssum[t] = s;
    __syncthreads();
    for (int off = 1; off < 1024; off <<= 1) {
        int v = (t >= off) ? ssum[t - off] : 0;
        __syncthreads();
        ssum[t] += v;
        __syncthreads();
    }
    int base = (t == 0) ? 0 : ssum[t-1];
#pragma unroll
    for (int k = 0; k < 16; k++) {
        int o = base + local[k];
        g_off[t*16 + k] = o;
        g_cur[t*16 + k] = o;
    }
    if (t == 1023) g_off[NN] = ssum[1023];
}

__global__ void scatter_kernel(const int* __restrict__ eidx) {
    int e = blockIdx.x * 256 + threadIdx.x;
    if (e < E_) {
        int d = eidx[E_ + e];
        int p = atomicAdd(&g_cur[d], 1);
        g_eorder[p] = e;
    }
}

// ---------------- per-node message aggregation: upd[n,l,f] ----------------
__global__ __launch_bounds__(128) void upd_kernel(
    const float* __restrict__ esh, const float* __restrict__ efeat,
    const float* __restrict__ Wrad, const int* __restrict__ eidx)
{
    int n = blockIdx.x;
    int f = threadIdx.x;
    __shared__ float sW[RR*FF];
    __shared__ int sE[256];
    for (int t = f; t < RR*FF; t += 128) sW[t] = Wrad[t];
    int beg = g_off[n], end = g_off[n+1];
    int deg = end - beg;
    for (int t = f; t < deg && t < 256; t += 128) sE[t] = g_eorder[beg + t];
    __syncthreads();
    if (f == 0 && deg > 1 && deg <= 256) {
        // deterministic accumulation order (ascending edge id)
        for (int a = 1; a < deg; a++) {
            int v = sE[a]; int b = a - 1;
            while (b >= 0 && sE[b] > v) { sE[b+1] = sE[b]; b--; }
            sE[b+1] = v;
        }
    }
    __syncthreads();
    float acc[LL];
#pragma unroll
    for (int l = 0; l < LL; l++) acc[l] = 0.f;
    for (int p = 0; p < deg; p++) {
        int e = (deg <= 256) ? sE[p] : g_eorder[beg + p];
        int s = eidx[e];
        float rw = 0.f;
#pragma unroll
        for (int r = 0; r < RR; r++) rw = fmaf(efeat[(long)e*RR + r], sW[r*FF + f], rw);
        float tv = g_hW[(long)s*FF + f] * rw;
#pragma unroll
        for (int l = 0; l < LL; l++) acc[l] = fmaf(esh[(long)e*LL + l], tv, acc[l]);
    }
#pragma unroll
    for (int l = 0; l < LL; l++) g_upd[(long)n*DOUT + l*FF + f] = acc[l];
}

// ---------------- epilogues ----------------
__global__ void add_h_kernel(const float* __restrict__ h) {
    int n = blockIdx.x, f = threadIdx.x;
    g_hlocal[(long)n*DOUT + f] += h[(long)n*FF + f];
}

__global__ void add_hm_kernel() {
    int i = blockIdx.x; int g = blockIdx.y*128 + threadIdx.x;
    g_hhier[(long)i*DOUT + g] += g_hm[(long)i*DOUT + g];
}

// ---------------- mask MLP: m = sigmoid(relu(hs@W1+b1)@W2+b2) ----------------
__global__ __launch_bounds__(64) void mlp_kernel(
    const float* __restrict__ W1, const float* __restrict__ b1,
    const float* __restrict__ W2, const float* __restrict__ b2,
    float* __restrict__ out_m)
{
    int n = blockIdx.x, t = threadIdx.x;
    __shared__ float sh_[FF];
    __shared__ float red[2];
    sh_[t]      = g_hlocal[(long)n*DOUT + t];
    sh_[t + 64] = g_hlocal[(long)n*DOUT + t + 64];
    __syncthreads();
    float a = b1[t];
#pragma unroll 8
    for (int f2 = 0; f2 < FF; f2++) a = fmaf(sh_[f2], W1[f2*HID + t], a);
    a = fmaxf(a, 0.f);
    float v = a * W2[t];
#pragma unroll
    for (int o = 16; o; o >>= 1) v += __shfl_down_sync(0xffffffffu, v, o);
    if ((t & 31) == 0) red[t >> 5] = v;
    __syncthreads();
    if (t == 0) {
        float x = red[0] + red[1] + b2[0];
        float mv = 1.f / (1.f + expf(-x));
        g_m[n] = mv;
        out_m[n] = mv;
    }
}

// ---------------- exact top-K rank: count strictly-greater (tie: lower idx) ----------------
__global__ __launch_bounds__(256) void rank_count_kernel() {
    __shared__ float sm[1024];
    int i = blockIdx.x * 256 + threadIdx.x;
    float mi = g_m[i];
    int jb = blockIdx.y * 1024;
    for (int t = threadIdx.x; t < 1024; t += 256) sm[t] = g_m[jb + t];
    __syncthreads();
    int cnt = 0;
#pragma unroll 8
    for (int jj = 0; jj < 1024; jj++) {
        float mj = sm[jj];
        int j = jb + jj;
        cnt += (mj > mi) || (mj == mi && j < i);
    }
    atomicAdd(&g_cntrank[i], cnt);
}

__global__ void mark_master_kernel() {
    int i = blockIdx.x * 256 + threadIdx.x;
    if (i < NN) g_ismaster[i] = (g_cntrank[i] < KM) ? 1 : 0;
}

__global__ __launch_bounds__(1024) void scan_master(float* __restrict__ out_mi) {
    __shared__ int ssum[1024];
    int t = threadIdx.x;
    int local[16];
    int s = 0;
#pragma unroll
    for (int k = 0; k < 16; k++) { local[k] = s; s += (int)g_ismaster[t*16 + k]; }
    ssum[t] = s;
    __syncthreads();
    for (int off = 1; off < 1024; off <<= 1) {
        int v = (t >= off) ? ssum[t - off] : 0;
        __syncthreads();
        ssum[t] += v;
        __syncthreads();
    }
    int base = (t == 0) ? 0 : ssum[t-1];
#pragma unroll
    for (int k = 0; k < 16; k++) {
        int idx = t*16 + k;
        if (g_ismaster[idx]) {
            int pos = base + local[k];
            g_master[pos] = idx;
            g_rank[idx] = pos;
            out_mi[pos] = (float)idx;
        } else {
            g_rank[idx] = KM;
        }
    }
}

// ---------------- induced adjacency among masters (src->dst) ----------------
__global__ void adj_kernel(const int* __restrict__ eidx) {
    int e = blockIdx.x * 256 + threadIdx.x;
    if (e < E_) {
        int rs = g_rank[eidx[e]];
        int rd = g_rank[eidx[E_ + e]];
        if (rs < KM && rd < KM) g_adj[(long)rs*KM + rd] = 1;
    }
}

// ---------------- gather masters ----------------
__global__ void gather_hm_kernel() {
    int i = blockIdx.x; int g = blockIdx.y*128 + threadIdx.x;
    g_hm[(long)i*DOUT + g] = g_hlocal[(long)g_master[i]*DOUT + g];
}

__global__ void gather_posm_kernel(const float* __restrict__ pos) {
    int t = blockIdx.x * 256 + threadIdx.x;
    if (t < KM*3) {
        int i = t / 3, c = t % 3;
        g_posm[t] = pos[(long)g_master[i]*3 + c];
    }
}

// ---------------- q/k projections ----------------
__global__ __launch_bounds__(64) void qk_kernel(
    const float* __restrict__ Wq, const float* __restrict__ Wk)
{
    int i = blockIdx.x, j = threadIdx.x;
    __shared__ float sh_[FF];
    sh_[j] = g_hm[(long)i*DOUT + j];
    sh_[j + 64] = g_hm[(long)i*DOUT + j + 64];
    __syncthreads();
    float q = 0.f, k = 0.f;
#pragma unroll 8
    for (int f = 0; f < FF; f++) {
        float hv = sh_[f];
        q = fmaf(hv, Wq[f*DA_ + j], q);
        k = fmaf(hv, Wk[f*DA_ + j], k);
    }
    g_q[(long)i*DA_ + j] = q;
    g_k[(long)i*DA_ + j] = k;
}

// ---------------- attention + A_virtual output ----------------
__global__ __launch_bounds__(256) void attn_kernel(float* __restrict__ out_av) {
    __shared__ float sq[16][65];
    __shared__ float sk[16][65];
    int bi = blockIdx.y * 16, bj = blockIdx.x * 16;
    int tid = threadIdx.x;
    for (int t = tid; t < 16*64; t += 256) {
        sq[t >> 6][t & 63] = g_q[(long)(bi + (t >> 6))*DA_ + (t & 63)];
        sk[t >> 6][t & 63] = g_k[(long)(bj + (t >> 6))*DA_ + (t & 63)];
    }
    __syncthreads();
    int ti = tid >> 4, tj = tid & 15;
    float d = 0.f;
#pragma unroll 8
    for (int x = 0; x < DA_; x++) d = fmaf(sq[ti][x], sk[tj][x], d);
    float A = 1.f / (1.f + expf(-d * 0.125f));
    out_av[(long)(bi + ti)*KM + (bj + tj)] = (A > 0.5f) ? A : 0.f;
}

// ---------------- receiver adjacency A_rec = adj_master^T ----------------
__global__ void arec_kernel(const float* __restrict__ av) {
    long idx = (long)blockIdx.x * 256 + threadIdx.x;
    int i = (int)(idx / KM), j = (int)(idx % KM);
    bool b = (i != j) &&
             (g_adj[(long)j*KM + i] || av[(long)i*KM + j] > 0.f || av[(long)j*KM + i] > 0.f);
    g_arec[idx] = b ? 1 : 0;
}

// ---------------- hn = h_m @ W_node_h  (K x 1152 x 128), 8 rows/block ----------------
__global__ __launch_bounds__(128) void gemm_hn_kernel(const float* __restrict__ Wnh) {
    int r0 = blockIdx.x * 8;
    int f = threadIdx.x;
    __shared__ float sA[8][DOUT];
    for (int t = f; t < 8*DOUT; t += 128) {
        int rr = t / DOUT, cc = t % DOUT;
        sA[rr][cc] = g_hm[(long)(r0 + rr)*DOUT + cc];
    }
    __syncthreads();
    float acc[8];
#pragma unroll
    for (int rr = 0; rr < 8; rr++) acc[rr] = 0.f;
    for (int kk = 0; kk < DOUT; kk++) {
        float b = Wnh[kk*FF + f];
#pragma unroll
        for (int rr = 0; rr < 8; rr++) acc[rr] = fmaf(sA[rr][kk], b, acc[rr]);
    }
#pragma unroll
    for (int rr = 0; rr < 8; rr++) g_hn[(long)(r0 + rr)*FF + f] = acc[rr];
}

// ---------------- K x K pair aggregation: upd_m[i,l,f] ----------------
__global__ __launch_bounds__(128) void pair_kernel(const float* __restrict__ Wrh) {
    int i0 = blockIdx.x * 2;
    int f = threadIdx.x;
    __shared__ float sposm[KM*3];
    __shared__ float s_sh[2][128][12];   // 9 used, padded for float4 access
    __shared__ float s_rad[2][128][8];
    __shared__ unsigned char s_a[2][128];
    for (int t = f; t < KM*3; t += 128) sposm[t] = g_posm[t];
    float wf[8];
#pragma unroll
    for (int rn = 0; rn < 8; rn++) wf[rn] = Wrh[rn*FF + f];
    __syncthreads();
    float pix[2], piy[2], piz[2];
#pragma unroll
    for (int ii = 0; ii < 2; ii++) {
        pix[ii] = sposm[(i0+ii)*3 + 0];
        piy[ii] = sposm[(i0+ii)*3 + 1];
        piz[ii] = sposm[(i0+ii)*3 + 2];
    }
    float acc[2][LL];
#pragma unroll
    for (int ii = 0; ii < 2; ii++)
#pragma unroll
        for (int l = 0; l < LL; l++) acc[ii][l] = 0.f;
    const float cb = sqrtf(2.f / 5.f);

    for (int jb = 0; jb < KM; jb += 128) {
        int j = jb + f;
        float pjx = sposm[j*3], pjy = sposm[j*3+1], pjz = sposm[j*3+2];
#pragma unroll
        for (int ii = 0; ii < 2; ii++) {
            unsigned char a = g_arec[(long)(i0+ii)*KM + j];
            s_a[ii][f] = a;
            if (a) {
                float vx = pjx - pix[ii], vy = pjy - piy[ii], vz = pjz - piz[ii];
                float r = sqrtf(vx*vx + vy*vy + vz*vz);
                float inv = 1.f / fmaxf(r, 1e-9f);
                float ux = vx*inv, uy = vy*inv, uz = vz*inv;
                s_sh[ii][f][0] = 1.f;
                s_sh[ii][f][1] = ux;
                s_sh[ii][f][2] = uy;
                s_sh[ii][f][3] = uz;
                s_sh[ii][f][4] = ux*uy;
                s_sh[ii][f][5] = uy*uz;
                s_sh[ii][f][6] = 3.f*uz*uz - 1.f;
                s_sh[ii][f][7] = ux*uz;
                s_sh[ii][f][8] = ux*ux - uy*uy;
#pragma unroll
                for (int rn = 0; rn < 8; rn++)
                    s_rad[ii][f][rn] = cb * sinf((float)(rn+1) * PI_F * r * 0.2f) * inv;
            }
        }
        __syncthreads();
        for (int jj = 0; jj < 128; jj++) {
            int a0 = s_a[0][jj], a1 = s_a[1][jj];
            if (!(a0 | a1)) continue;
            float hnf = g_hn[(long)(jb + jj)*FF + f];
#pragma unroll
            for (int ii = 0; ii < 2; ii++) {
                if ((ii == 0 && a0) || (ii == 1 && a1)) {
                    float4 r0 = *(const float4*)(&s_rad[ii][jj][0]);
                    float4 r1 = *(const float4*)(&s_rad[ii][jj][4]);
                    float rw = 0.f;
                    rw = fmaf(r0.x, wf[0], rw); rw = fmaf(r0.y, wf[1], rw);
                    rw = fmaf(r0.z, wf[2], rw); rw = fmaf(r0.w, wf[3], rw);
                    rw = fmaf(r1.x, wf[4], rw); rw = fmaf(r1.y, wf[5], rw);
                    rw = fmaf(r1.z, wf[6], rw); rw = fmaf(r1.w, wf[7], rw);
                    float tmv = hnf * rw;
                    float4 s0 = *(const float4*)(&s_sh[ii][jj][0]);
                    float4 s1 = *(const float4*)(&s_sh[ii][jj][4]);
                    float  s8 = s_sh[ii][jj][8];
                    acc[ii][0] = fmaf(s0.x, tmv, acc[ii][0]);
                    acc[ii][1] = fmaf(s0.y, tmv, acc[ii][1]);
                    acc[ii][2] = fmaf(s0.z, tmv, acc[ii][2]);
                    acc[ii][3] = fmaf(s0.w, tmv, acc[ii][3]);
                    acc[ii][4] = fmaf(s1.x, tmv, acc[ii][4]);
                    acc[ii][5] = fmaf(s1.y, tmv, acc[ii][5]);
                    acc[ii][6] = fmaf(s1.z, tmv, acc[ii][6]);
                    acc[ii][7] = fmaf(s1.w, tmv, acc[ii][7]);
                    acc[ii][8] = fmaf(s8,   tmv, acc[ii][8]);
                }
            }
        }
        __syncthreads();
    }
#pragma unroll
    for (int ii = 0; ii < 2; ii++)
#pragma unroll
        for (int l = 0; l < LL; l++)
            g_updm[(long)(i0+ii)*DOUT + l*FF + f] = acc[ii][l];
}

// ---------------- final combine ----------------
__global__ __launch_bounds__(128) void final_kernel(float* __restrict__ out) {
    int n = blockIdx.x;
    int g = blockIdx.y * 128 + threadIdx.x;
    long idx = (long)n*DOUT + g;
    float mm = g_m[n];
    float hl = g_hlocal[idx];
    int rk = g_rank[n];
    float he = (rk < KM) ? g_hhier[(long)rk*DOUT + g] : 0.f;
    out[idx] = (1.f - mm) * hl + mm * he;
}

// ---------------- launcher ----------------
extern "C" void kernel_launch(void* const* d_in, const int* in_sizes, int n_in,
                              void* d_out, int out_size)
{
    const float* h     = (const float*)d_in[0];
    const float* pos   = (const float*)d_in[1];
    const float* esh   = (const float*)d_in[2];
    const float* efeat = (const float*)d_in[3];
    const float* Wnl   = (const float*)d_in[4];
    const float* Wrl   = (const float*)d_in[5];
    const float* Wpl   = (const float*)d_in[6];
    const float* W1    = (const float*)d_in[7];
    const float* b1    = (const float*)d_in[8];
    const float* W2    = (const float*)d_in[9];
    const float* b2    = (const float*)d_in[10];
    const float* Wq    = (const float*)d_in[11];
    const float* Wk    = (const float*)d_in[12];
    const float* Wnh   = (const float*)d_in[13];
    const float* Wrh   = (const float*)d_in[14];
    const float* Wph   = (const float*)d_in[15];
    const int*   eidx  = (const int*)d_in[16];
    float* out = (float*)d_out;

    const size_t OFF_AV = (size_t)NN * DOUT;
    const size_t OFF_M  = OFF_AV + (size_t)KM * KM;
    const size_t OFF_MI = OFF_M + (size_t)NN;

    // symbol addresses (host API, not a stream op; capture-safe)
    void *p_hW = 0, *p_upd = 0, *p_hlocal = 0, *p_updm = 0, *p_hhier = 0;
    cudaGetSymbolAddress(&p_hW, g_hW);
    cudaGetSymbolAddress(&p_upd, g_upd);
    cudaGetSymbolAddress(&p_hlocal, g_hlocal);
    cudaGetSymbolAddress(&p_updm, g_updm);
    cudaGetSymbolAddress(&p_hhier, g_hhier);

    // 0) zero scratch
    zero_kernel<<<4608, 256>>>();

    // 1) hW = h @ W_node_l   (16384 x 128 x 128)
    sgemm2<<<dim3(1, 128, 1), 256>>>(h, Wnl, (float*)p_hW, NN, FF, FF);

    // 2) CSR build (group edges by dst, deterministic order)
    count_kernel<<<E_/256, 256>>>(eidx);
    scan_counts<<<1, 1024>>>();
    scatter_kernel<<<E_/256, 256>>>(eidx);

    // 3) message aggregation -> g_upd (N, 9*128)
    upd_kernel<<<NN, 128>>>(esh, efeat, Wrl, eidx);

    // 4) h_local = upd @ W_prod_l + pad(h)    (16384 x 1152 x 1152)
    sgemm2<<<dim3(DOUT/128, NN/128, 1), 256>>>((const float*)p_upd, Wpl,
                                               (float*)p_hlocal, NN, DOUT, DOUT);
    add_h_kernel<<<NN, 128>>>(h);

    // 5) mask MLP -> g_m, out m
    mlp_kernel<<<NN, 64>>>(W1, b1, W2, b2, out + OFF_M);

    // 6) exact top-K via full rank counting
    rank_count_kernel<<<dim3(NN/256, 16), 256>>>();
    mark_master_kernel<<<NN/256, 256>>>();
    scan_master<<<1, 1024>>>(out + OFF_MI);

    // 7) induced adjacency + master gathers
    adj_kernel<<<E_/256, 256>>>(eidx);
    gather_hm_kernel<<<dim3(KM, DOUT/128), 128>>>();
    gather_posm_kernel<<<(KM*3 + 255)/256, 256>>>(pos);

    // 8) virtual attention -> out A_virtual, then A_rec
    qk_kernel<<<KM, 64>>>(Wq, Wk);
    attn_kernel<<<dim3(KM/16, KM/16), 256>>>(out + OFF_AV);
    arec_kernel<<<(KM*KM)/256, 256>>>(out + OFF_AV);

    // 9) hierarchical update over K x K pairs
    gemm_hn_kernel<<<KM/8, 128>>>(Wnh);
    pair_kernel<<<KM/2, 128>>>(Wrh);

    // 10) h_hier = upd_m @ W_prod_h + h_m   (1024 x 1152 x 1152, split-K=4)
    sgemm2<<<dim3(DOUT/128, KM/128, 4), 256>>>((const float*)p_updm, Wph,
                                               (float*)p_hhier, KM, DOUT, DOUT);
    add_hm_kernel<<<dim3(KM, DOUT/128), 128>>>();

    // 11) combine -> out h_final
    final_kernel<<<dim3(NN, DOUT/128), 128>>>(out);
}

// round 14
// speedup vs baseline: 1.1411x; 1.0506x over previous
#include <cuda_runtime.h>
#include <cuda_bf16.h>
#include <math.h>
#include <stdint.h>

#define NN    16384
#define E_    131072
#define FF    128
#define LL    9
#define RR    8
#define DOUT  1152
#define KM    1024
#define HID   64
#define DA_   64
#define PI_F  3.14159265358979323846f

// ---------------- scratch (device globals; no runtime allocation) ----------------
__device__ float g_hW[(long)NN*FF];
__device__ float g_upd[(long)NN*DOUT];
__device__ float g_hlocal[(long)NN*DOUT];
__device__ float g_m[NN];
__device__ int   g_cnt[NN];
__device__ int   g_cntrank[NN];
__device__ int   g_off[NN+1];
__device__ int   g_cur[NN];
__device__ int   g_eorder[E_];
__device__ int   g_rank[NN];
__device__ unsigned char g_ismaster[NN];
__device__ int   g_master[KM];
__device__ unsigned char g_adj[(long)KM*KM];
__device__ unsigned char g_arec[(long)KM*KM];
__device__ float g_hm[(long)KM*DOUT];
__device__ float g_posm[KM*3];
__device__ float g_hn[(long)KM*FF];
__device__ float g_q[(long)KM*DA_];
__device__ float g_k[(long)KM*DA_];
__device__ float g_updm[(long)KM*DOUT];
__device__ float g_hhier[(long)KM*DOUT];

// bf16x3 split operands (16B aligned for cp.async)
__device__ __align__(16) __nv_bfloat16 g_A0[(long)NN*DOUT];
__device__ __align__(16) __nv_bfloat16 g_A1[(long)NN*DOUT];
__device__ __align__(16) __nv_bfloat16 g_A2[(long)NN*DOUT];
__device__ __align__(16) __nv_bfloat16 g_Am0[(long)KM*DOUT];
__device__ __align__(16) __nv_bfloat16 g_Am1[(long)KM*DOUT];
__device__ __align__(16) __nv_bfloat16 g_Am2[(long)KM*DOUT];
__device__ __align__(16) __nv_bfloat16 g_BL0[(long)DOUT*DOUT];
__device__ __align__(16) __nv_bfloat16 g_BL1[(long)DOUT*DOUT];
__device__ __align__(16) __nv_bfloat16 g_BL2[(long)DOUT*DOUT];
__device__ __align__(16) __nv_bfloat16 g_BH0[(long)DOUT*DOUT];
__device__ __align__(16) __nv_bfloat16 g_BH1[(long)DOUT*DOUT];
__device__ __align__(16) __nv_bfloat16 g_BH2[(long)DOUT*DOUT];

// ---------------- helpers ----------------
__device__ __forceinline__ uint32_t smem_to_u32(const void* p) {
    uint32_t a;
    asm("{ .reg .u64 t; cvta.to.shared.u64 t, %1; cvt.u32.u64 %0, t; }" : "=r"(a) : "l"(p));
    return a;
}
#define CP_ASYNC16(sa, ga) asm volatile("cp.async.cg.shared.global [%0], [%1], 16;" :: "r"(sa), "l"(ga))
#define CP_COMMIT() asm volatile("cp.async.commit_group;" ::: "memory")
#define CP_WAIT0()  asm volatile("cp.async.wait_group 0;" ::: "memory")
#define CP_WAIT1()  asm volatile("cp.async.wait_group 1;" ::: "memory")

__device__ __forceinline__ void ldsm4(uint32_t& r0, uint32_t& r1, uint32_t& r2, uint32_t& r3, uint32_t addr) {
    asm volatile("ldmatrix.sync.aligned.m8n8.x4.shared.b16 {%0,%1,%2,%3}, [%4];"
        : "=r"(r0), "=r"(r1), "=r"(r2), "=r"(r3) : "r"(addr));
}
__device__ __forceinline__ void ldsm2(uint32_t& r0, uint32_t& r1, uint32_t addr) {
    asm volatile("ldmatrix.sync.aligned.m8n8.x2.shared.b16 {%0,%1}, [%2];"
        : "=r"(r0), "=r"(r1) : "r"(addr));
}
__device__ __forceinline__ void mma16816(float* c, uint32_t a0, uint32_t a1, uint32_t a2, uint32_t a3,
                                         uint32_t b0, uint32_t b1) {
    asm volatile("mma.sync.aligned.m16n8k16.row.col.f32.bf16.bf16.f32 "
        "{%0,%1,%2,%3}, {%4,%5,%6,%7}, {%8,%9}, {%0,%1,%2,%3};"
        : "+f"(c[0]), "+f"(c[1]), "+f"(c[2]), "+f"(c[3])
        : "r"(a0), "r"(a1), "r"(a2), "r"(a3), "r"(b0), "r"(b1));
}

// ---------------- f32 -> bf16x3 split ----------------
__global__ void split3_kernel(const float* __restrict__ X,
                              __nv_bfloat16* __restrict__ A0,
                              __nv_bfloat16* __restrict__ A1,
                              __nv_bfloat16* __restrict__ A2, long n)
{
    long i = (long)blockIdx.x * 256 + threadIdx.x;
    if (i < n) {
        float x = X[i];
        __nv_bfloat16 b0 = __float2bfloat16(x);
        float r = x - __bfloat162float(b0);
        __nv_bfloat16 b1 = __float2bfloat16(r);
        float r2 = r - __bfloat162float(b1);
        A0[i] = b0; A1[i] = b1; A2[i] = __float2bfloat16(r2);
    }
}

// W[k][n] -> Bt[n][k] splits (transpose + split)
__global__ void splitWT_kernel(const float* __restrict__ W,
                               __nv_bfloat16* __restrict__ B0,
                               __nv_bfloat16* __restrict__ B1,
                               __nv_bfloat16* __restrict__ B2)
{
    long i = (long)blockIdx.x * 256 + threadIdx.x;
    if (i < (long)DOUT*DOUT) {
        int n = (int)(i / DOUT), k = (int)(i % DOUT);
        float x = W[(long)k*DOUT + n];
        __nv_bfloat16 b0 = __float2bfloat16(x);
        float r = x - __bfloat162float(b0);
        __nv_bfloat16 b1 = __float2bfloat16(r);
        float r2 = r - __bfloat162float(b1);
        B0[i] = b0; B1[i] = b1; B2[i] = __float2bfloat16(r2);
    }
}

// ---------------- bf16x3 HMMA GEMM: C[:, col_off + bx*128 ...] = sum_{6 pairs} Ai @ Bj^T ----
// 128x128 tile, BK=16, 256 threads (8 warps, 2x4), cp.async double buffer.
// Smem tile: 128 rows x 24 halves (48B stride).
#define GTILE 6144                // 128*48
#define GBUF  36864               // 6*GTILE
#define GSME  73728               // 2*GBUF

__global__ __launch_bounds__(256, 2) void mma_gemm(
    const __nv_bfloat16* __restrict__ A0, const __nv_bfloat16* __restrict__ A1,
    const __nv_bfloat16* __restrict__ A2,
    const __nv_bfloat16* __restrict__ B0, const __nv_bfloat16* __restrict__ B1,
    const __nv_bfloat16* __restrict__ B2,
    float* __restrict__ C, int nchunks, int col_off)
{
    extern __shared__ char smem[];
    const uint32_t sb = smem_to_u32(smem);
    const int tid = threadIdx.x, lane = tid & 31, wid = tid >> 5;
    const int warp_m = wid & 1, warp_n = wid >> 1;
    const long rbase = (long)blockIdx.y * 128;
    const long nbase = (long)col_off + (long)blockIdx.x * 128;
    const int  c0 = blockIdx.z * nchunks;
    const bool splitk = (gridDim.z > 1);

    const __nv_bfloat16* APs[3] = {A0, A1, A2};
    const __nv_bfloat16* BPs[3] = {B0, B1, B2};

    // per-thread cp.async assignments: 6 tiles x 128 rows x 2 16B-chunks = 1536 / 256
    const char* gsrc[6];
    uint32_t sdst[6];
#pragma unroll
    for (int j = 0; j < 6; j++) {
        int idx = j*256 + tid;
        int tile = idx >> 8, rem = idx & 255, r = rem >> 1, g = rem & 1;
        const __nv_bfloat16* src = (tile < 3) ? APs[tile] : BPs[tile - 3];
        long grow = (tile < 3) ? (rbase + r) : (nbase + r);
        gsrc[j] = (const char*)(src + grow * DOUT) + (long)c0 * 32 + g * 16;
        sdst[j] = sb + tile * GTILE + r * 48 + g * 16;
    }

    float acc[4][4][4];
#pragma unroll
    for (int mt = 0; mt < 4; mt++)
#pragma unroll
        for (int nt = 0; nt < 4; nt++)
#pragma unroll
            for (int q = 0; q < 4; q++) acc[mt][nt][q] = 0.f;

    const uint32_t a_lane = (uint32_t)((lane & 15)*48 + (lane >> 4)*16 + warp_m*(64*48));
    const uint32_t b_lane = (uint32_t)((lane & 7)*48 + ((lane >> 3) & 1)*16 + warp_n*(32*48)) + 3*GTILE;

    // prologue: chunk 0 -> buf 0
#pragma unroll
    for (int j = 0; j < 6; j++) CP_ASYNC16(sdst[j], gsrc[j]);
    CP_COMMIT();

    for (int c = 0; c < nchunks; c++) {
        if (c + 1 < nchunks) {
            uint32_t bo = (uint32_t)(((c + 1) & 1)) * GBUF;
            long go = (long)(c + 1) * 32;
#pragma unroll
            for (int j = 0; j < 6; j++) CP_ASYNC16(sdst[j] + bo, gsrc[j] + go);
            CP_COMMIT();
            CP_WAIT1();
        } else {
            CP_WAIT0();
        }
        __syncthreads();

        const uint32_t bufo = (uint32_t)(c & 1) * GBUF;
        uint32_t af[4][4], bfr[4][2];
        const int PIa[6] = {0,0,0,1,1,2};
        const int PJa[6] = {0,1,2,0,1,0};
#pragma unroll
        for (int p = 0; p < 6; p++) {
            if (p == 0 || PIa[p] != PIa[p-1]) {
#pragma unroll
                for (int mt = 0; mt < 4; mt++)
                    ldsm4(af[mt][0], af[mt][1], af[mt][2], af[mt][3],
                          sb + bufo + (uint32_t)PIa[p]*GTILE + a_lane + mt*768);
            }
#pragma unroll
            for (int nt = 0; nt < 4; nt++)
                ldsm2(bfr[nt][0], bfr[nt][1],
                      sb + bufo + (uint32_t)PJa[p]*GTILE + b_lane + nt*384);
#pragma unroll
            for (int mt = 0; mt < 4; mt++)
#pragma unroll
                for (int nt = 0; nt < 4; nt++)
                    mma16816(acc[mt][nt], af[mt][0], af[mt][1], af[mt][2], af[mt][3],
                             bfr[nt][0], bfr[nt][1]);
        }
        __syncthreads();
    }

    // epilogue
    const long crow = rbase + warp_m*64 + (lane >> 2);
    const long ccol = nbase + warp_n*32 + (lane & 3)*2;
    if (!splitk) {
#pragma unroll
        for (int mt = 0; mt < 4; mt++)
#pragma unroll
            for (int nt = 0; nt < 4; nt++) {
                float* p0 = C + (crow + mt*16) * DOUT + ccol + nt*8;
                *(float2*)p0 = make_float2(acc[mt][nt][0], acc[mt][nt][1]);
                *(float2*)(p0 + 8*DOUT) = make_float2(acc[mt][nt][2], acc[mt][nt][3]);
            }
    } else {
#pragma unroll
        for (int mt = 0; mt < 4; mt++)
#pragma unroll
            for (int nt = 0; nt < 4; nt++) {
                float* p0 = C + (crow + mt*16) * DOUT + ccol + nt*8;
                atomicAdd(p0,     acc[mt][nt][0]);
                atomicAdd(p0 + 1, acc[mt][nt][1]);
                atomicAdd(p0 + 8*DOUT,     acc[mt][nt][2]);
                atomicAdd(p0 + 8*DOUT + 1, acc[mt][nt][3]);
            }
    }
}

// ---------------- zero scratch that must start at 0 ----------------
__global__ void zero_kernel() {
    long i = (long)blockIdx.x * 256 + threadIdx.x;
    if (i < NN) { g_cnt[i] = 0; g_cntrank[i] = 0; }
    if (i < (long)KM*KM) g_adj[i] = 0;
    if (i < (long)KM*DOUT) g_hhier[i] = 0.f;
}

// ---------------- fp32 SGEMM via packed f32x2 (exact path: hW + h_local cols 0-127) --------
__device__ __forceinline__ unsigned long long ffma2(
    unsigned long long a, unsigned long long b, unsigned long long c)
{
    unsigned long long d;
    asm("fma.rn.f32x2 %0, %1, %2, %3;" : "=l"(d) : "l"(a), "l"(b), "l"(c));
    return d;
}
__device__ __forceinline__ unsigned long long pack2(float x, float y) {
    unsigned long long r;
    asm("mov.b64 %0, {%1, %2};" : "=l"(r) : "f"(x), "f"(y));
    return r;
}
__device__ __forceinline__ void unpack2(unsigned long long v, float& lo, float& hi) {
    asm("mov.b64 {%0, %1}, %2;" : "=f"(lo), "=f"(hi) : "l"(v));
}

__global__ __launch_bounds__(256, 2) void sgemm2(
    const float* __restrict__ A, const float* __restrict__ B,
    float* __restrict__ C, int M, int Nc, int Kc)
{
    __shared__ unsigned long long As2[2][8][128];
    __shared__ float Bs[2][8][128];
    const int tid = threadIdx.x;
    const int tx = tid & 15;
    const int ty = tid >> 4;
    const long crow0 = (long)blockIdx.y * 128;
    const long ccol0 = (long)blockIdx.x * 128;
    const int aRow = tid >> 1;
    const int aCol = (tid & 1) << 2;
    const int bRow = tid >> 5;
    const int bCol = (tid & 31) << 2;
    const float* Ag = A + (crow0 + aRow) * (long)Kc + aCol;
    const float* Bg = B + ccol0 + bCol + (long)bRow * Nc;
    const int kchunk = Kc / gridDim.z;
    const int kbeg = blockIdx.z * kchunk;
    const int nT = kchunk / 8;

    unsigned long long acc[8][4];
#pragma unroll
    for (int i = 0; i < 8; i++)
#pragma unroll
        for (int k = 0; k < 4; k++) acc[i][k] = 0ull;

    float4 a4 = *(const float4*)(Ag + kbeg);
    float4 b4 = *(const float4*)(Bg + (long)kbeg * Nc);
    As2[0][aCol+0][aRow] = pack2(a4.x, a4.x);
    As2[0][aCol+1][aRow] = pack2(a4.y, a4.y);
    As2[0][aCol+2][aRow] = pack2(a4.z, a4.z);
    As2[0][aCol+3][aRow] = pack2(a4.w, a4.w);
    *(float4*)(&Bs[0][bRow][bCol]) = b4;
    __syncthreads();

    for (int t = 0; t < nT; t++) {
        const int cur = t & 1;
        const int nxt = cur ^ 1;
        if (t + 1 < nT) {
            int k0 = kbeg + (t + 1) * 8;
            a4 = *(const float4*)(Ag + k0);
            b4 = *(const float4*)(Bg + (long)k0 * Nc);
        }
#pragma unroll
        for (int kk = 0; kk < 8; kk++) {
            unsigned long long ar[8], br[4];
#pragma unroll
            for (int i = 0; i < 4; i++) {
                ulonglong2 p = *(const ulonglong2*)(&As2[cur][kk][ty*8 + 2*i]);
                ar[2*i]   = p.x;
                ar[2*i+1] = p.y;
            }
#pragma unroll
            for (int k = 0; k < 4; k++)
                br[k] = *(const unsigned long long*)(&Bs[cur][kk][tx*2 + 32*k]);
#pragma unroll
            for (int i = 0; i < 8; i++)
#pragma unroll
                for (int k = 0; k < 4; k++)
                    acc[i][k] = ffma2(ar[i], br[k], acc[i][k]);
        }
        if (t + 1 < nT) {
            As2[nxt][aCol+0][aRow] = pack2(a4.x, a4.x);
            As2[nxt][aCol+1][aRow] = pack2(a4.y, a4.y);
            As2[nxt][aCol+2][aRow] = pack2(a4.z, a4.z);
            As2[nxt][aCol+3][aRow] = pack2(a4.w, a4.w);
            *(float4*)(&Bs[nxt][bRow][bCol]) = b4;
        }
        __syncthreads();
    }

#pragma unroll
    for (int i = 0; i < 8; i++) {
        long row = crow0 + ty*8 + i;
        float* Cp = C + row * (long)Nc + ccol0;
#pragma unroll
        for (int k = 0; k < 4; k++) {
            float lo, hi;
            unpack2(acc[i][k], lo, hi);
            *(float2*)(&Cp[tx*2 + 32*k]) = make_float2(lo, hi);
        }
    }
}

// ---------------- CSR build (edges grouped by dst) ----------------
__global__ void count_kernel(const int* __restrict__ eidx) {
    int e = blockIdx.x * 256 + threadIdx.x;
    if (e < E_) atomicAdd(&g_cnt[eidx[E_ + e]], 1);
}

__global__ __launch_bounds__(1024) void scan_counts() {
    __shared__ int ssum[1024];
    int t = threadIdx.x;
    int local[16];
    int s = 0;
#pragma unroll
    for (int k = 0; k < 16; k++) { local[k] = s; s += g_cnt[t*16 + k]; }
    ssum[t] = s;
    __syncthreads();
    for (int off = 1; off < 1024; off <<= 1) {
        int v = (t >= off) ? ssum[t - off] : 0;
        __syncthreads();
        ssum[t] += v;
        __syncthreads();
    }
    int base = (t == 0) ? 0 : ssum[t-1];
#pragma unroll
    for (int k = 0; k < 16; k++) {
        int o = base + local[k];
        g_off[t*16 + k] = o;
        g_cur[t*16 + k] = o;
    }
    if (t == 1023) g_off[NN] = ssum[1023];
}

__global__ void scatter_kernel(const int* __restrict__ eidx) {
    int e = blockIdx.x * 256 + threadIdx.x;
    if (e < E_) {
        int d = eidx[E_ + e];
        int p = atomicAdd(&g_cur[d], 1);
        g_eorder[p] = e;
    }
}

// ---------------- per-node message aggregation: upd[n,l,f] ----------------
__global__ __launch_bounds__(128) void upd_kernel(
    const float* __restrict__ esh, const float* __restrict__ efeat,
    const float* __restrict__ Wrad, const int* __restrict__ eidx)
{
    int n = blockIdx.x;
    int f = threadIdx.x;
    __shared__ float sW[RR*FF];
    __shared__ int sE[256];
    for (int t = f; t < RR*FF; t += 128) sW[t] = Wrad[t];
    int beg = g_off[n], end = g_off[n+1];
    int deg = end - beg;
    for (int t = f; t < deg && t < 256; t += 128) sE[t] = g_eorder[beg + t];
    __syncthreads();
    if (f == 0 && deg > 1 && deg <= 256) {
        for (int a = 1; a < deg; a++) {
            int v = sE[a]; int b = a - 1;
            while (b >= 0 && sE[b] > v) { sE[b+1] = sE[b]; b--; }
            sE[b+1] = v;
        }
    }
    __syncthreads();
    float acc[LL];
#pragma unroll
    for (int l = 0; l < LL; l++) acc[l] = 0.f;
    for (int p = 0; p < deg; p++) {
        int e = (deg <= 256) ? sE[p] : g_eorder[beg + p];
        int s = eidx[e];
        float rw = 0.f;
#pragma unroll
        for (int r = 0; r < RR; r++) rw = fmaf(efeat[(long)e*RR + r], sW[r*FF + f], rw);
        float tv = g_hW[(long)s*FF + f] * rw;
#pragma unroll
        for (int l = 0; l < LL; l++) acc[l] = fmaf(esh[(long)e*LL + l], tv, acc[l]);
    }
#pragma unroll
    for (int l = 0; l < LL; l++) g_upd[(long)n*DOUT + l*FF + f] = acc[l];
}

// ---------------- epilogues ----------------
__global__ void add_h_kernel(const float* __restrict__ h) {
    int n = blockIdx.x, f = threadIdx.x;
    g_hlocal[(long)n*DOUT + f] += h[(long)n*FF + f];
}

__global__ void add_hm_kernel() {
    int i = blockIdx.x; int g = blockIdx.y*128 + threadIdx.x;
    g_hhier[(long)i*DOUT + g] += g_hm[(long)i*DOUT + g];
}

// ---------------- mask MLP ----------------
__global__ __launch_bounds__(64) void mlp_kernel(
    const float* __restrict__ W1, const float* __restrict__ b1,
    const float* __restrict__ W2, const float* __restrict__ b2,
    float* __restrict__ out_m)
{
    int n = blockIdx.x, t = threadIdx.x;
    __shared__ float sh_[FF];
    __shared__ float red[2];
    sh_[t]      = g_hlocal[(long)n*DOUT + t];
    sh_[t + 64] = g_hlocal[(long)n*DOUT + t + 64];
    __syncthreads();
    float a = b1[t];
#pragma unroll 8
    for (int f2 = 0; f2 < FF; f2++) a = fmaf(sh_[f2], W1[f2*HID + t], a);
    a = fmaxf(a, 0.f);
    float v = a * W2[t];
#pragma unroll
    for (int o = 16; o; o >>= 1) v += __shfl_down_sync(0xffffffffu, v, o);
    if ((t & 31) == 0) red[t >> 5] = v;
    __syncthreads();
    if (t == 0) {
        float x = red[0] + red[1] + b2[0];
        float mv = 1.f / (1.f + expf(-x));
        g_m[n] = mv;
        out_m[n] = mv;
    }
}

// ---------------- exact top-K rank ----------------
__global__ __launch_bounds__(256) void rank_count_kernel() {
    __shared__ float sm[1024];
    int i = blockIdx.x * 256 + threadIdx.x;
    float mi = g_m[i];
    int jb = blockIdx.y * 1024;
    for (int t = threadIdx.x; t < 1024; t += 256) sm[t] = g_m[jb + t];
    __syncthreads();
    int cnt = 0;
#pragma unroll 8
    for (int jj = 0; jj < 1024; jj++) {
        float mj = sm[jj];
        int j = jb + jj;
        cnt += (mj > mi) || (mj == mi && j < i);
    }
    atomicAdd(&g_cntrank[i], cnt);
}

__global__ void mark_master_kernel() {
    int i = blockIdx.x * 256 + threadIdx.x;
    if (i < NN) g_ismaster[i] = (g_cntrank[i] < KM) ? 1 : 0;
}

__global__ __launch_bounds__(1024) void scan_master(float* __restrict__ out_mi) {
    __shared__ int ssum[1024];
    int t = threadIdx.x;
    int local[16];
    int s = 0;
#pragma unroll
    for (int k = 0; k < 16; k++) { local[k] = s; s += (int)g_ismaster[t*16 + k]; }
    ssum[t] = s;
    __syncthreads();
    for (int off = 1; off < 1024; off <<= 1) {
        int v = (t >= off) ? ssum[t - off] : 0;
        __syncthreads();
        ssum[t] += v;
        __syncthreads();
    }
    int base = (t == 0) ? 0 : ssum[t-1];
#pragma unroll
    for (int k = 0; k < 16; k++) {
        int idx = t*16 + k;
        if (g_ismaster[idx]) {
            int pos = base + local[k];
            g_master[pos] = idx;
            g_rank[idx] = pos;
            out_mi[pos] = (float)idx;
        } else {
            g_rank[idx] = KM;
        }
    }
}

// ---------------- induced adjacency among masters ----------------
__global__ void adj_kernel(const int* __restrict__ eidx) {
    int e = blockIdx.x * 256 + threadIdx.x;
    if (e < E_) {
        int rs = g_rank[eidx[e]];
        int rd = g_rank[eidx[E_ + e]];
        if (rs < KM && rd < KM) g_adj[(long)rs*KM + rd] = 1;
    }
}

// ---------------- gather masters ----------------
__global__ void gather_hm_kernel() {
    int i = blockIdx.x; int g = blockIdx.y*128 + threadIdx.x;
    g_hm[(long)i*DOUT + g] = g_hlocal[(long)g_master[i]*DOUT + g];
}

__global__ void gather_posm_kernel(const float* __restrict__ pos) {
    int t = blockIdx.x * 256 + threadIdx.x;
    if (t < KM*3) {
        int i = t / 3, c = t % 3;
        g_posm[t] = pos[(long)g_master[i]*3 + c];
    }
}

// ---------------- q/k projections ----------------
__global__ __launch_bounds__(64) void qk_kernel(
    const float* __restrict__ Wq, const float* __restrict__ Wk)
{
    int i = blockIdx.x, j = threadIdx.x;
    __shared__ float sh_[FF];
    sh_[j] = g_hm[(long)i*DOUT + j];
    sh_[j + 64] = g_hm[(long)i*DOUT + j + 64];
    __syncthreads();
    float q = 0.f, k = 0.f;
#pragma unroll 8
    for (int f = 0; f < FF; f++) {
        float hv = sh_[f];
        q = fmaf(hv, Wq[f*DA_ + j], q);
        k = fmaf(hv, Wk[f*DA_ + j], k);
    }
    g_q[(long)i*DA_ + j] = q;
    g_k[(long)i*DA_ + j] = k;
}

// ---------------- attention + A_virtual output ----------------
__global__ __launch_bounds__(256) void attn_kernel(float* __restrict__ out_av) {
    __shared__ float sq[16][65];
    __shared__ float sk[16][65];
    int bi = blockIdx.y * 16, bj = blockIdx.x * 16;
    int tid = threadIdx.x;
    for (int t = tid; t < 16*64; t += 256) {
        sq[t >> 6][t & 63] = g_q[(long)(bi + (t >> 6))*DA_ + (t & 63)];
        sk[t >> 6][t & 63] = g_k[(long)(bj + (t >> 6))*DA_ + (t & 63)];
    }
    __syncthreads();
    int ti = tid >> 4, tj = tid & 15;
    float d = 0.f;
#pragma unroll 8
    for (int x = 0; x < DA_; x++) d = fmaf(sq[ti][x], sk[tj][x], d);
    float A = 1.f / (1.f + expf(-d * 0.125f));
    out_av[(long)(bi + ti)*KM + (bj + tj)] = (A > 0.5f) ? A : 0.f;
}

// ---------------- receiver adjacency ----------------
__global__ void arec_kernel(const float* __restrict__ av) {
    long idx = (long)blockIdx.x * 256 + threadIdx.x;
    int i = (int)(idx / KM), j = (int)(idx % KM);
    bool b = (i != j) &&
             (g_adj[(long)j*KM + i] || av[(long)i*KM + j] > 0.f || av[(long)j*KM + i] > 0.f);
    g_arec[idx] = b ? 1 : 0;
}

// ---------------- hn = h_m @ W_node_h ----------------
__global__ __launch_bounds__(128) void gemm_hn_kernel(const float* __restrict__ Wnh) {
    int r0 = blockIdx.x * 8;
    int f = threadIdx.x;
    __shared__ float sA[8][DOUT];
    for (int t = f; t < 8*DOUT; t += 128) {
        int rr = t / DOUT, cc = t % DOUT;
        sA[rr][cc] = g_hm[(long)(r0 + rr)*DOUT + cc];
    }
    __syncthreads();
    float acc[8];
#pragma unroll
    for (int rr = 0; rr < 8; rr++) acc[rr] = 0.f;
    for (int kk = 0; kk < DOUT; kk++) {
        float b = Wnh[kk*FF + f];
#pragma unroll
        for (int rr = 0; rr < 8; rr++) acc[rr] = fmaf(sA[rr][kk], b, acc[rr]);
    }
#pragma unroll
    for (int rr = 0; rr < 8; rr++) g_hn[(long)(r0 + rr)*FF + f] = acc[rr];
}

// ---------------- K x K pair aggregation ----------------
__global__ __launch_bounds__(128) void pair_kernel(const float* __restrict__ Wrh) {
    int i0 = blockIdx.x * 2;
    int f = threadIdx.x;
    __shared__ float sposm[KM*3];
    __shared__ float s_sh[2][128][12];
    __shared__ float s_rad[2][128][8];
    __shared__ unsigned char s_a[2][128];
    for (int t = f; t < KM*3; t += 128) sposm[t] = g_posm[t];
    float wf[8];
#pragma unroll
    for (int rn = 0; rn < 8; rn++) wf[rn] = Wrh[rn*FF + f];
    __syncthreads();
    float pix[2], piy[2], piz[2];
#pragma unroll
    for (int ii = 0; ii < 2; ii++) {
        pix[ii] = sposm[(i0+ii)*3 + 0];
        piy[ii] = sposm[(i0+ii)*3 + 1];
        piz[ii] = sposm[(i0+ii)*3 + 2];
    }
    float acc[2][LL];
#pragma unroll
    for (int ii = 0; ii < 2; ii++)
#pragma unroll
        for (int l = 0; l < LL; l++) acc[ii][l] = 0.f;
    const float cb = sqrtf(2.f / 5.f);

    for (int jb = 0; jb < KM; jb += 128) {
        int j = jb + f;
        float pjx = sposm[j*3], pjy = sposm[j*3+1], pjz = sposm[j*3+2];
#pragma unroll
        for (int ii = 0; ii < 2; ii++) {
            unsigned char a = g_arec[(long)(i0+ii)*KM + j];
            s_a[ii][f] = a;
            if (a) {
                float vx = pjx - pix[ii], vy = pjy - piy[ii], vz = pjz - piz[ii];
                float r = sqrtf(vx*vx + vy*vy + vz*vz);
                float inv = 1.f / fmaxf(r, 1e-9f);
                float ux = vx*inv, uy = vy*inv, uz = vz*inv;
                s_sh[ii][f][0] = 1.f;
                s_sh[ii][f][1] = ux;
                s_sh[ii][f][2] = uy;
                s_sh[ii][f][3] = uz;
                s_sh[ii][f][4] = ux*uy;
                s_sh[ii][f][5] = uy*uz;
                s_sh[ii][f][6] = 3.f*uz*uz - 1.f;
                s_sh[ii][f][7] = ux*uz;
                s_sh[ii][f][8] = ux*ux - uy*uy;
#pragma unroll
                for (int rn = 0; rn < 8; rn++)
                    s_rad[ii][f][rn] = cb * sinf((float)(rn+1) * PI_F * r * 0.2f) * inv;
            }
        }
        __syncthreads();
        for (int jj = 0; jj < 128; jj++) {
            int a0 = s_a[0][jj], a1 = s_a[1][jj];
            if (!(a0 | a1)) continue;
            float hnf = g_hn[(long)(jb + jj)*FF + f];
#pragma unroll
            for (int ii = 0; ii < 2; ii++) {
                if ((ii == 0 && a0) || (ii == 1 && a1)) {
                    float4 r0 = *(const float4*)(&s_rad[ii][jj][0]);
                    float4 r1 = *(const float4*)(&s_rad[ii][jj][4]);
                    float rw = 0.f;
                    rw = fmaf(r0.x, wf[0], rw); rw = fmaf(r0.y, wf[1], rw);
                    rw = fmaf(r0.z, wf[2], rw); rw = fmaf(r0.w, wf[3], rw);
                    rw = fmaf(r1.x, wf[4], rw); rw = fmaf(r1.y, wf[5], rw);
                    rw = fmaf(r1.z, wf[6], rw); rw = fmaf(r1.w, wf[7], rw);
                    float tmv = hnf * rw;
                    float4 s0 = *(const float4*)(&s_sh[ii][jj][0]);
                    float4 s1 = *(const float4*)(&s_sh[ii][jj][4]);
                    float  s8 = s_sh[ii][jj][8];
                    acc[ii][0] = fmaf(s0.x, tmv, acc[ii][0]);
                    acc[ii][1] = fmaf(s0.y, tmv, acc[ii][1]);
                    acc[ii][2] = fmaf(s0.z, tmv, acc[ii][2]);
                    acc[ii][3] = fmaf(s0.w, tmv, acc[ii][3]);
                    acc[ii][4] = fmaf(s1.x, tmv, acc[ii][4]);
                    acc[ii][5] = fmaf(s1.y, tmv, acc[ii][5]);
                    acc[ii][6] = fmaf(s1.z, tmv, acc[ii][6]);
                    acc[ii][7] = fmaf(s1.w, tmv, acc[ii][7]);
                    acc[ii][8] = fmaf(s8,   tmv, acc[ii][8]);
                }
            }
        }
        __syncthreads();
    }
#pragma unroll
    for (int ii = 0; ii < 2; ii++)
#pragma unroll
        for (int l = 0; l < LL; l++)
            g_updm[(long)(i0+ii)*DOUT + l*FF + f] = acc[ii][l];
}

// ---------------- final combine ----------------
__global__ __launch_bounds__(128) void final_kernel(float* __restrict__ out) {
    int n = blockIdx.x;
    int g = blockIdx.y * 128 + threadIdx.x;
    long idx = (long)n*DOUT + g;
    float mm = g_m[n];
    float hl = g_hlocal[idx];
    int rk = g_rank[n];
    float he = (rk < KM) ? g_hhier[(long)rk*DOUT + g] : 0.f;
    out[idx] = (1.f - mm) * hl + mm * he;
}

// ---------------- launcher ----------------
extern "C" void kernel_launch(void* const* d_in, const int* in_sizes, int n_in,
                              void* d_out, int out_size)
{
    const float* h     = (const float*)d_in[0];
    const float* pos   = (const float*)d_in[1];
    const float* esh   = (const float*)d_in[2];
    const float* efeat = (const float*)d_in[3];
    const float* Wnl   = (const float*)d_in[4];
    const float* Wrl   = (const float*)d_in[5];
    const float* Wpl   = (const float*)d_in[6];
    const float* W1    = (const float*)d_in[7];
    const float* b1    = (const float*)d_in[8];
    const float* W2    = (const float*)d_in[9];
    const float* b2    = (const float*)d_in[10];
    const float* Wq    = (const float*)d_in[11];
    const float* Wk    = (const float*)d_in[12];
    const float* Wnh   = (const float*)d_in[13];
    const float* Wrh   = (const float*)d_in[14];
    const float* Wph   = (const float*)d_in[15];
    const int*   eidx  = (const int*)d_in[16];
    float* out = (float*)d_out;

    const size_t OFF_AV = (size_t)NN * DOUT;
    const size_t OFF_M  = OFF_AV + (size_t)KM * KM;
    const size_t OFF_MI = OFF_M + (size_t)NN;

    void *p_hW=0, *p_upd=0, *p_hlocal=0, *p_updm=0, *p_hhier=0;
    void *pA0=0,*pA1=0,*pA2=0,*pAm0=0,*pAm1=0,*pAm2=0;
    void *pBL0=0,*pBL1=0,*pBL2=0,*pBH0=0,*pBH1=0,*pBH2=0;
    cudaGetSymbolAddress(&p_hW, g_hW);
    cudaGetSymbolAddress(&p_upd, g_upd);
    cudaGetSymbolAddress(&p_hlocal, g_hlocal);
    cudaGetSymbolAddress(&p_updm, g_updm);
    cudaGetSymbolAddress(&p_hhier, g_hhier);
    cudaGetSymbolAddress(&pA0, g_A0);  cudaGetSymbolAddress(&pA1, g_A1);  cudaGetSymbolAddress(&pA2, g_A2);
    cudaGetSymbolAddress(&pAm0, g_Am0); cudaGetSymbolAddress(&pAm1, g_Am1); cudaGetSymbolAddress(&pAm2, g_Am2);
    cudaGetSymbolAddress(&pBL0, g_BL0); cudaGetSymbolAddress(&pBL1, g_BL1); cudaGetSymbolAddress(&pBL2, g_BL2);
    cudaGetSymbolAddress(&pBH0, g_BH0); cudaGetSymbolAddress(&pBH1, g_BH1); cudaGetSymbolAddress(&pBH2, g_BH2);

    cudaFuncSetAttribute(mma_gemm, cudaFuncAttributeMaxDynamicSharedMemorySize, GSME);

    // 0) zero scratch
    zero_kernel<<<4608, 256>>>();

    // 1) hW = h @ W_node_l (exact fp32)
    sgemm2<<<dim3(1, 128, 1), 256>>>(h, Wnl, (float*)p_hW, NN, FF, FF);

    // 2) CSR build
    count_kernel<<<E_/256, 256>>>(eidx);
    scan_counts<<<1, 1024>>>();
    scatter_kernel<<<E_/256, 256>>>(eidx);

    // weight splits (independent; issue early)
    splitWT_kernel<<<(DOUT*DOUT + 255)/256, 256>>>(Wpl, (__nv_bfloat16*)pBL0, (__nv_bfloat16*)pBL1, (__nv_bfloat16*)pBL2);
    splitWT_kernel<<<(DOUT*DOUT + 255)/256, 256>>>(Wph, (__nv_bfloat16*)pBH0, (__nv_bfloat16*)pBH1, (__nv_bfloat16*)pBH2);

    // 3) message aggregation -> g_upd
    upd_kernel<<<NN, 128>>>(esh, efeat, Wrl, eidx);

    // 4) h_local: cols 0-127 EXACT fp32 (threshold-critical: m, top-K, q/k);
    //    cols 128-1151 via bf16x3 HMMA. Then += pad(h).
    sgemm2<<<dim3(1, NN/128, 1), 256>>>((const float*)p_upd, Wpl,
                                        (float*)p_hlocal, NN, DOUT, DOUT);
    split3_kernel<<<(int)(((long)NN*DOUT + 255)/256), 256>>>((const float*)p_upd,
        (__nv_bfloat16*)pA0, (__nv_bfloat16*)pA1, (__nv_bfloat16*)pA2, (long)NN*DOUT);
    mma_gemm<<<dim3((DOUT-FF)/128, NN/128, 1), 256, GSME>>>(
        (const __nv_bfloat16*)pA0, (const __nv_bfloat16*)pA1, (const __nv_bfloat16*)pA2,
        (const __nv_bfloat16*)pBL0, (const __nv_bfloat16*)pBL1, (const __nv_bfloat16*)pBL2,
        (float*)p_hlocal, DOUT/16, FF);
    add_h_kernel<<<NN, 128>>>(h);

    // 5) mask MLP (exact)
    mlp_kernel<<<NN, 64>>>(W1, b1, W2, b2, out + OFF_M);

    // 6) exact top-K
    rank_count_kernel<<<dim3(NN/256, 16), 256>>>();
    mark_master_kernel<<<NN/256, 256>>>();
    scan_master<<<1, 1024>>>(out + OFF_MI);

    // 7) adjacency + gathers
    adj_kernel<<<E_/256, 256>>>(eidx);
    gather_hm_kernel<<<dim3(KM, DOUT/128), 128>>>();
    gather_posm_kernel<<<(KM*3 + 255)/256, 256>>>(pos);

    // 8) virtual attention (exact: hms cols are fp32-exact)
    qk_kernel<<<KM, 64>>>(Wq, Wk);
    attn_kernel<<<dim3(KM/16, KM/16), 256>>>(out + OFF_AV);
    arec_kernel<<<(KM*KM)/256, 256>>>(out + OFF_AV);

    // 9) hierarchical update
    gemm_hn_kernel<<<KM/8, 128>>>(Wnh);
    pair_kernel<<<KM/2, 128>>>(Wrh);

    // 10) h_hier = upd_m @ W_prod_h (bf16x3 HMMA, split-K=4 atomic) + h_m
    split3_kernel<<<(int)(((long)KM*DOUT + 255)/256), 256>>>((const float*)p_updm,
        (__nv_bfloat16*)pAm0, (__nv_bfloat16*)pAm1, (__nv_bfloat16*)pAm2, (long)KM*DOUT);
    mma_gemm<<<dim3(DOUT/128, KM/128, 4), 256, GSME>>>(
        (const __nv_bfloat16*)pAm0, (const __nv_bfloat16*)pAm1, (const __nv_bfloat16*)pAm2,
        (const __nv_bfloat16*)pBH0, (const __nv_bfloat16*)pBH1, (const __nv_bfloat16*)pBH2,
        (float*)p_hhier, (DOUT/16)/4, 0);
    add_hm_kernel<<<dim3(KM, DOUT/128), 128>>>();

    // 11) combine
    final_kernel<<<dim3(NN, DOUT/128), 128>>>(out);
}

// round 17
// speedup vs baseline: 1.3682x; 1.1990x over previous
#include <cuda_runtime.h>
#include <cuda_bf16.h>
#include <math.h>
#include <stdint.h>

#define NN    16384
#define E_    131072
#define FF    128
#define LL    9
#define RR    8
#define DOUT  1152
#define KM    1024
#define HID   64
#define DA_   64
#define PI_F  3.14159265358979323846f

// ---------------- scratch (device globals; no runtime allocation) ----------------
__device__ float g_hW[(long)NN*FF];
__device__ float g_upd[(long)NN*DOUT];
__device__ float g_hlocal[(long)NN*DOUT];
__device__ float g_m[NN];
__device__ int   g_cnt[NN];
__device__ int   g_cntrank[NN];
__device__ int   g_off[NN+1];
__device__ int   g_cur[NN];
__device__ int   g_eorder[E_];
__device__ int   g_rank[NN];
__device__ unsigned char g_ismaster[NN];
__device__ int   g_master[KM];
__device__ unsigned char g_adj[(long)KM*KM];
__device__ unsigned char g_arec[(long)KM*KM];
__device__ float g_hm[(long)KM*DOUT];
__device__ float g_posm[KM*3];
__device__ float g_hn[(long)KM*FF];
__device__ float g_q[(long)KM*DA_];
__device__ float g_k[(long)KM*DA_];
__device__ float g_updm[(long)KM*DOUT];
__device__ float g_hhier[(long)KM*DOUT];

// bf16x2 split operands (16B aligned for cp.async)
__device__ __align__(16) __nv_bfloat16 g_A0[(long)NN*DOUT];
__device__ __align__(16) __nv_bfloat16 g_A1[(long)NN*DOUT];
__device__ __align__(16) __nv_bfloat16 g_Am0[(long)KM*DOUT];
__device__ __align__(16) __nv_bfloat16 g_Am1[(long)KM*DOUT];
__device__ __align__(16) __nv_bfloat16 g_BL0[(long)DOUT*DOUT];
__device__ __align__(16) __nv_bfloat16 g_BL1[(long)DOUT*DOUT];
__device__ __align__(16) __nv_bfloat16 g_BH0[(long)DOUT*DOUT];
__device__ __align__(16) __nv_bfloat16 g_BH1[(long)DOUT*DOUT];

// ---------------- helpers ----------------
__device__ __forceinline__ uint32_t smem_to_u32(const void* p) {
    uint32_t a;
    asm("{ .reg .u64 t; cvta.to.shared.u64 t, %1; cvt.u32.u64 %0, t; }" : "=r"(a) : "l"(p));
    return a;
}
#define CP_ASYNC16(sa, ga) asm volatile("cp.async.cg.shared.global [%0], [%1], 16;" :: "r"(sa), "l"(ga))
#define CP_COMMIT() asm volatile("cp.async.commit_group;" ::: "memory")
#define CP_WAIT0()  asm volatile("cp.async.wait_group 0;" ::: "memory")
#define CP_WAIT1()  asm volatile("cp.async.wait_group 1;" ::: "memory")

__device__ __forceinline__ void ldsm4(uint32_t& r0, uint32_t& r1, uint32_t& r2, uint32_t& r3, uint32_t addr) {
    asm volatile("ldmatrix.sync.aligned.m8n8.x4.shared.b16 {%0,%1,%2,%3}, [%4];"
        : "=r"(r0), "=r"(r1), "=r"(r2), "=r"(r3) : "r"(addr));
}
__device__ __forceinline__ void ldsm2(uint32_t& r0, uint32_t& r1, uint32_t addr) {
    asm volatile("ldmatrix.sync.aligned.m8n8.x2.shared.b16 {%0,%1}, [%2];"
        : "=r"(r0), "=r"(r1) : "r"(addr));
}
__device__ __forceinline__ void mma16816(float* c, uint32_t a0, uint32_t a1, uint32_t a2, uint32_t a3,
                                         uint32_t b0, uint32_t b1) {
    asm volatile("mma.sync.aligned.m16n8k16.row.col.f32.bf16.bf16.f32 "
        "{%0,%1,%2,%3}, {%4,%5,%6,%7}, {%8,%9}, {%0,%1,%2,%3};"
        : "+f"(c[0]), "+f"(c[1]), "+f"(c[2]), "+f"(c[3])
        : "r"(a0), "r"(a1), "r"(a2), "r"(a3), "r"(b0), "r"(b1));
}

// ---------------- f32 -> bf16x2 split ----------------
__global__ void split2_kernel(const float* __restrict__ X,
                              __nv_bfloat16* __restrict__ A0,
                              __nv_bfloat16* __restrict__ A1, long n)
{
    long i = (long)blockIdx.x * 256 + threadIdx.x;
    if (i < n) {
        float x = X[i];
        __nv_bfloat16 b0 = __float2bfloat16(x);
        float r = x - __bfloat162float(b0);
        A0[i] = b0; A1[i] = __float2bfloat16(r);
    }
}

// W[k][n] -> Bt[n][k] bf16x2 splits (transpose + split)
__global__ void splitWT2_kernel(const float* __restrict__ W,
                                __nv_bfloat16* __restrict__ B0,
                                __nv_bfloat16* __restrict__ B1)
{
    long i = (long)blockIdx.x * 256 + threadIdx.x;
    if (i < (long)DOUT*DOUT) {
        int n = (int)(i / DOUT), k = (int)(i % DOUT);
        float x = W[(long)k*DOUT + n];
        __nv_bfloat16 b0 = __float2bfloat16(x);
        float r = x - __bfloat162float(b0);
        B0[i] = b0; B1[i] = __float2bfloat16(r);
    }
}

// ---------------- bf16x2 HMMA GEMM: C[:, col_off + bx*128 ...] = A0B0^T + A0B1^T + A1B0^T ----
// 128x128 tile, BK=16, 256 threads (8 warps, 2x4), cp.async double buffer.
// Smem: 4 tiles of 128 rows x 24 halves (48B stride, conflict-free ldmatrix).
// Tile order in smem: [A0, A1, B0, B1].
#define GTILE 6144                // 128*48
#define GBUF  24576               // 4*GTILE
#define GSME  49152               // 2*GBUF

__global__ __launch_bounds__(256, 2) void mma_gemm(
    const __nv_bfloat16* __restrict__ A0, const __nv_bfloat16* __restrict__ A1,
    const __nv_bfloat16* __restrict__ B0, const __nv_bfloat16* __restrict__ B1,
    float* __restrict__ C, int nchunks, int col_off)
{
    extern __shared__ char smem[];
    const uint32_t sb = smem_to_u32(smem);
    const int tid = threadIdx.x, lane = tid & 31, wid = tid >> 5;
    const int warp_m = wid & 1, warp_n = wid >> 1;
    const long rbase = (long)blockIdx.y * 128;
    const long nbase = (long)col_off + (long)blockIdx.x * 128;
    const int  c0 = blockIdx.z * nchunks;
    const bool splitk = (gridDim.z > 1);

    const __nv_bfloat16* APs[2] = {A0, A1};
    const __nv_bfloat16* BPs[2] = {B0, B1};

    // per-thread cp.async assignments: 4 tiles x 128 rows x 2 16B-chunks = 1024 / 256
    const char* gsrc[4];
    uint32_t sdst[4];
#pragma unroll
    for (int j = 0; j < 4; j++) {
        int idx = j*256 + tid;
        int tile = idx >> 8, rem = idx & 255, r = rem >> 1, g = rem & 1;
        const __nv_bfloat16* src = (tile < 2) ? APs[tile] : BPs[tile - 2];
        long grow = (tile < 2) ? (rbase + r) : (nbase + r);
        gsrc[j] = (const char*)(src + grow * DOUT) + (long)c0 * 32 + g * 16;
        sdst[j] = sb + tile * GTILE + r * 48 + g * 16;
    }

    float acc[4][4][4];
#pragma unroll
    for (int mt = 0; mt < 4; mt++)
#pragma unroll
        for (int nt = 0; nt < 4; nt++)
#pragma unroll
            for (int q = 0; q < 4; q++) acc[mt][nt][q] = 0.f;

    const uint32_t a_lane = (uint32_t)((lane & 15)*48 + (lane >> 4)*16 + warp_m*(64*48));
    const uint32_t b_lane = (uint32_t)((lane & 7)*48 + ((lane >> 3) & 1)*16 + warp_n*(32*48)) + 2*GTILE;

    // prologue: chunk 0 -> buf 0
#pragma unroll
    for (int j = 0; j < 4; j++) CP_ASYNC16(sdst[j], gsrc[j]);
    CP_COMMIT();

    for (int c = 0; c < nchunks; c++) {
        if (c + 1 < nchunks) {
            uint32_t bo = (uint32_t)(((c + 1) & 1)) * GBUF;
            long go = (long)(c + 1) * 32;
#pragma unroll
            for (int j = 0; j < 4; j++) CP_ASYNC16(sdst[j] + bo, gsrc[j] + go);
            CP_COMMIT();
            CP_WAIT1();
        } else {
            CP_WAIT0();
        }
        __syncthreads();

        const uint32_t bufo = (uint32_t)(c & 1) * GBUF;
        uint32_t af[4][4], bfr[4][2];
        // products: (A0,B0), (A0,B1), (A1,B0)
        const int PIa[3] = {0,0,1};
        const int PJa[3] = {0,1,0};
#pragma unroll
        for (int p = 0; p < 3; p++) {
            if (p == 0 || PIa[p] != PIa[p-1]) {
#pragma unroll
                for (int mt = 0; mt < 4; mt++)
                    ldsm4(af[mt][0], af[mt][1], af[mt][2], af[mt][3],
                          sb + bufo + (uint32_t)PIa[p]*GTILE + a_lane + mt*768);
            }
#pragma unroll
            for (int nt = 0; nt < 4; nt++)
                ldsm2(bfr[nt][0], bfr[nt][1],
                      sb + bufo + (uint32_t)PJa[p]*GTILE + b_lane + nt*384);
#pragma unroll
            for (int mt = 0; mt < 4; mt++)
#pragma unroll
                for (int nt = 0; nt < 4; nt++)
                    mma16816(acc[mt][nt], af[mt][0], af[mt][1], af[mt][2], af[mt][3],
                             bfr[nt][0], bfr[nt][1]);
        }
        __syncthreads();
    }

    // epilogue
    const long crow = rbase + warp_m*64 + (lane >> 2);
    const long ccol = nbase + warp_n*32 + (lane & 3)*2;
    if (!splitk) {
#pragma unroll
        for (int mt = 0; mt < 4; mt++)
#pragma unroll
            for (int nt = 0; nt < 4; nt++) {
                float* p0 = C + (crow + mt*16) * DOUT + ccol + nt*8;
                *(float2*)p0 = make_float2(acc[mt][nt][0], acc[mt][nt][1]);
                *(float2*)(p0 + 8*DOUT) = make_float2(acc[mt][nt][2], acc[mt][nt][3]);
            }
    } else {
#pragma unroll
        for (int mt = 0; mt < 4; mt++)
#pragma unroll
            for (int nt = 0; nt < 4; nt++) {
                float* p0 = C + (crow + mt*16) * DOUT + ccol + nt*8;
                atomicAdd(p0,     acc[mt][nt][0]);
                atomicAdd(p0 + 1, acc[mt][nt][1]);
                atomicAdd(p0 + 8*DOUT,     acc[mt][nt][2]);
                atomicAdd(p0 + 8*DOUT + 1, acc[mt][nt][3]);
            }
    }
}

// ---------------- zero scratch that must start at 0 ----------------
__global__ void zero_kernel() {
    long i = (long)blockIdx.x * 256 + threadIdx.x;
    if (i < NN) { g_cnt[i] = 0; g_cntrank[i] = 0; }
    if (i < (long)KM*KM) g_adj[i] = 0;
    if (i < (long)KM*DOUT) g_hhier[i] = 0.f;
}

// ---------------- fp32 SGEMM via packed f32x2 (exact path: hW + h_local cols 0-127) --------
__device__ __forceinline__ unsigned long long ffma2(
    unsigned long long a, unsigned long long b, unsigned long long c)
{
    unsigned long long d;
    asm("fma.rn.f32x2 %0, %1, %2, %3;" : "=l"(d) : "l"(a), "l"(b), "l"(c));
    return d;
}
__device__ __forceinline__ unsigned long long pack2(float x, float y) {
    unsigned long long r;
    asm("mov.b64 %0, {%1, %2};" : "=l"(r) : "f"(x), "f"(y));
    return r;
}
__device__ __forceinline__ void unpack2(unsigned long long v, float& lo, float& hi) {
    asm("mov.b64 {%0, %1}, %2;" : "=f"(lo), "=f"(hi) : "l"(v));
}

__global__ __launch_bounds__(256, 2) void sgemm2(
    const float* __restrict__ A, const float* __restrict__ B,
    float* __restrict__ C, int M, int Nc, int Kc)
{
    __shared__ unsigned long long As2[2][8][128];
    __shared__ float Bs[2][8][128];
    const int tid = threadIdx.x;
    const int tx = tid & 15;
    const int ty = tid >> 4;
    const long crow0 = (long)blockIdx.y * 128;
    const long ccol0 = (long)blockIdx.x * 128;
    const int aRow = tid >> 1;
    const int aCol = (tid & 1) << 2;
    const int bRow = tid >> 5;
    const int bCol = (tid & 31) << 2;
    const float* Ag = A + (crow0 + aRow) * (long)Kc + aCol;
    const float* Bg = B + ccol0 + bCol + (long)bRow * Nc;
    const int kchunk = Kc / gridDim.z;
    const int kbeg = blockIdx.z * kchunk;
    const int nT = kchunk / 8;

    unsigned long long acc[8][4];
#pragma unroll
    for (int i = 0; i < 8; i++)
#pragma unroll
        for (int k = 0; k < 4; k++) acc[i][k] = 0ull;

    float4 a4 = *(const float4*)(Ag + kbeg);
    float4 b4 = *(const float4*)(Bg + (long)kbeg * Nc);
    As2[0][aCol+0][aRow] = pack2(a4.x, a4.x);
    As2[0][aCol+1][aRow] = pack2(a4.y, a4.y);
    As2[0][aCol+2][aRow] = pack2(a4.z, a4.z);
    As2[0][aCol+3][aRow] = pack2(a4.w, a4.w);
    *(float4*)(&Bs[0][bRow][bCol]) = b4;
    __syncthreads();

    for (int t = 0; t < nT; t++) {
        const int cur = t & 1;
        const int nxt = cur ^ 1;
        if (t + 1 < nT) {
            int k0 = kbeg + (t + 1) * 8;
            a4 = *(const float4*)(Ag + k0);
            b4 = *(const float4*)(Bg + (long)k0 * Nc);
        }
#pragma unroll
        for (int kk = 0; kk < 8; kk++) {
            unsigned long long ar[8], br[4];
#pragma unroll
            for (int i = 0; i < 4; i++) {
                ulonglong2 p = *(const ulonglong2*)(&As2[cur][kk][ty*8 + 2*i]);
                ar[2*i]   = p.x;
                ar[2*i+1] = p.y;
            }
#pragma unroll
            for (int k = 0; k < 4; k++)
                br[k] = *(const unsigned long long*)(&Bs[cur][kk][tx*2 + 32*k]);
#pragma unroll
            for (int i = 0; i < 8; i++)
#pragma unroll
                for (int k = 0; k < 4; k++)
                    acc[i][k] = ffma2(ar[i], br[k], acc[i][k]);
        }
        if (t + 1 < nT) {
            As2[nxt][aCol+0][aRow] = pack2(a4.x, a4.x);
            As2[nxt][aCol+1][aRow] = pack2(a4.y, a4.y);
            As2[nxt][aCol+2][aRow] = pack2(a4.z, a4.z);
            As2[nxt][aCol+3][aRow] = pack2(a4.w, a4.w);
            *(float4*)(&Bs[nxt][bRow][bCol]) = b4;
        }
        __syncthreads();
    }

#pragma unroll
    for (int i = 0; i < 8; i++) {
        long row = crow0 + ty*8 + i;
        float* Cp = C + row * (long)Nc + ccol0;
#pragma unroll
        for (int k = 0; k < 4; k++) {
            float lo, hi;
            unpack2(acc[i][k], lo, hi);
            *(float2*)(&Cp[tx*2 + 32*k]) = make_float2(lo, hi);
        }
    }
}

// ---------------- CSR build (edges grouped by dst) ----------------
__global__ void count_kernel(const int* __restrict__ eidx) {
    int e = blockIdx.x * 256 + threadIdx.x;
    if (e < E_) atomicAdd(&g_cnt[eidx[E_ + e]], 1);
}

__global__ __launch_bounds__(1024) void scan_counts() {
    __shared__ int ssum[1024];
    int t = threadIdx.x;
    int local[16];
    int s = 0;
#pragma unroll
    for (int k = 0; k < 16; k++) { local[k] = s; s += g_cnt[t*16 + k]; }
    ssum[t] = s;
    __syncthreads();
    for (int off = 1; off < 1024; off <<= 1) {
        int v = (t >= off) ? ssum[t - off] : 0;
        __syncthreads();
        ssum[t] += v;
        __syncthreads();
    }
    int base = (t == 0) ? 0 : ssum[t-1];
#pragma unroll
    for (int k = 0; k < 16; k++) {
        int o = base + local[k];
        g_off[t*16 + k] = o;
        g_cur[t*16 + k] = o;
    }
    if (t == 1023) g_off[NN] = ssum[1023];
}

__global__ void scatter_kernel(const int* __restrict__ eidx) {
    int e = blockIdx.x * 256 + threadIdx.x;
    if (e < E_) {
        int d = eidx[E_ + e];
        int p = atomicAdd(&g_cur[d], 1);
        g_eorder[p] = e;
    }
}

// ---------------- per-node message aggregation: upd[n,l,f] ----------------
__global__ __launch_bounds__(128) void upd_kernel(
    const float* __restrict__ esh, const float* __restrict__ efeat,
    const float* __restrict__ Wrad, const int* __restrict__ eidx)
{
    int n = blockIdx.x;
    int f = threadIdx.x;
    __shared__ float sW[RR*FF];
    __shared__ int sE[256];
    for (int t = f; t < RR*FF; t += 128) sW[t] = Wrad[t];
    int beg = g_off[n], end = g_off[n+1];
    int deg = end - beg;
    for (int t = f; t < deg && t < 256; t += 128) sE[t] = g_eorder[beg + t];
    __syncthreads();
    if (f == 0 && deg > 1 && deg <= 256) {
        for (int a = 1; a < deg; a++) {
            int v = sE[a]; int b = a - 1;
            while (b >= 0 && sE[b] > v) { sE[b+1] = sE[b]; b--; }
            sE[b+1] = v;
        }
    }
    __syncthreads();
    float acc[LL];
#pragma unroll
    for (int l = 0; l < LL; l++) acc[l] = 0.f;
    for (int p = 0; p < deg; p++) {
        int e = (deg <= 256) ? sE[p] : g_eorder[beg + p];
        int s = eidx[e];
        float rw = 0.f;
#pragma unroll
        for (int r = 0; r < RR; r++) rw = fmaf(efeat[(long)e*RR + r], sW[r*FF + f], rw);
        float tv = g_hW[(long)s*FF + f] * rw;
#pragma unroll
        for (int l = 0; l < LL; l++) acc[l] = fmaf(esh[(long)e*LL + l], tv, acc[l]);
    }
#pragma unroll
    for (int l = 0; l < LL; l++) g_upd[(long)n*DOUT + l*FF + f] = acc[l];
}

// ---------------- epilogues ----------------
__global__ void add_h_kernel(const float* __restrict__ h) {
    int n = blockIdx.x, f = threadIdx.x;
    g_hlocal[(long)n*DOUT + f] += h[(long)n*FF + f];
}

__global__ void add_hm_kernel() {
    int i = blockIdx.x; int g = blockIdx.y*128 + threadIdx.x;
    g_hhier[(long)i*DOUT + g] += g_hm[(long)i*DOUT + g];
}

// ---------------- mask MLP ----------------
__global__ __launch_bounds__(64) void mlp_kernel(
    const float* __restrict__ W1, const float* __restrict__ b1,
    const float* __restrict__ W2, const float* __restrict__ b2,
    float* __restrict__ out_m)
{
    int n = blockIdx.x, t = threadIdx.x;
    __shared__ float sh_[FF];
    __shared__ float red[2];
    sh_[t]      = g_hlocal[(long)n*DOUT + t];
    sh_[t + 64] = g_hlocal[(long)n*DOUT + t + 64];
    __syncthreads();
    float a = b1[t];
#pragma unroll 8
    for (int f2 = 0; f2 < FF; f2++) a = fmaf(sh_[f2], W1[f2*HID + t], a);
    a = fmaxf(a, 0.f);
    float v = a * W2[t];
#pragma unroll
    for (int o = 16; o; o >>= 1) v += __shfl_down_sync(0xffffffffu, v, o);
    if ((t & 31) == 0) red[t >> 5] = v;
    __syncthreads();
    if (t == 0) {
        float x = red[0] + red[1] + b2[0];
        float mv = 1.f / (1.f + expf(-x));
        g_m[n] = mv;
        out_m[n] = mv;
    }
}

// ---------------- exact top-K rank ----------------
__global__ __launch_bounds__(256) void rank_count_kernel() {
    __shared__ float sm[1024];
    int i = blockIdx.x * 256 + threadIdx.x;
    float mi = g_m[i];
    int jb = blockIdx.y * 1024;
    for (int t = threadIdx.x; t < 1024; t += 256) sm[t] = g_m[jb + t];
    __syncthreads();
    int cnt = 0;
#pragma unroll 8
    for (int jj = 0; jj < 1024; jj++) {
        float mj = sm[jj];
        int j = jb + jj;
        cnt += (mj > mi) || (mj == mi && j < i);
    }
    atomicAdd(&g_cntrank[i], cnt);
}

__global__ void mark_master_kernel() {
    int i = blockIdx.x * 256 + threadIdx.x;
    if (i < NN) g_ismaster[i] = (g_cntrank[i] < KM) ? 1 : 0;
}

__global__ __launch_bounds__(1024) void scan_master(float* __restrict__ out_mi) {
    __shared__ int ssum[1024];
    int t = threadIdx.x;
    int local[16];
    int s = 0;
#pragma unroll
    for (int k = 0; k < 16; k++) { local[k] = s; s += (int)g_ismaster[t*16 + k]; }
    ssum[t] = s;
    __syncthreads();
    for (int off = 1; off < 1024; off <<= 1) {
        int v = (t >= off) ? ssum[t - off] : 0;
        __syncthreads();
        ssum[t] += v;
        __syncthreads();
    }
    int base = (t == 0) ? 0 : ssum[t-1];
#pragma unroll
    for (int k = 0; k < 16; k++) {
        int idx = t*16 + k;
        if (g_ismaster[idx]) {
            int pos = base + local[k];
            g_master[pos] = idx;
            g_rank[idx] = pos;
            out_mi[pos] = (float)idx;
        } else {
            g_rank[idx] = KM;
        }
    }
}

// ---------------- induced adjacency among masters ----------------
__global__ void adj_kernel(const int* __restrict__ eidx) {
    int e = blockIdx.x * 256 + threadIdx.x;
    if (e < E_) {
        int rs = g_rank[eidx[e]];
        int rd = g_rank[eidx[E_ + e]];
        if (rs < KM && rd < KM) g_adj[(long)rs*KM + rd] = 1;
    }
}

// ---------------- gather masters ----------------
__global__ void gather_hm_kernel() {
    int i = blockIdx.x; int g = blockIdx.y*128 + threadIdx.x;
    g_hm[(long)i*DOUT + g] = g_hlocal[(long)g_master[i]*DOUT + g];
}

__global__ void gather_posm_kernel(const float* __restrict__ pos) {
    int t = blockIdx.x * 256 + threadIdx.x;
    if (t < KM*3) {
        int i = t / 3, c = t % 3;
        g_posm[t] = pos[(long)g_master[i]*3 + c];
    }
}

// ---------------- q/k projections ----------------
__global__ __launch_bounds__(64) void qk_kernel(
    const float* __restrict__ Wq, const float* __restrict__ Wk)
{
    int i = blockIdx.x, j = threadIdx.x;
    __shared__ float sh_[FF];
    sh_[j] = g_hm[(long)i*DOUT + j];
    sh_[j + 64] = g_hm[(long)i*DOUT + j + 64];
    __syncthreads();
    float q = 0.f, k = 0.f;
#pragma unroll 8
    for (int f = 0; f < FF; f++) {
        float hv = sh_[f];
        q = fmaf(hv, Wq[f*DA_ + j], q);
        k = fmaf(hv, Wk[f*DA_ + j], k);
    }
    g_q[(long)i*DA_ + j] = q;
    g_k[(long)i*DA_ + j] = k;
}

// ---------------- attention + A_virtual output ----------------
__global__ __launch_bounds__(256) void attn_kernel(float* __restrict__ out_av) {
    __shared__ float sq[16][65];
    __shared__ float sk[16][65];
    int bi = blockIdx.y * 16, bj = blockIdx.x * 16;
    int tid = threadIdx.x;
    for (int t = tid; t < 16*64; t += 256) {
        sq[t >> 6][t & 63] = g_q[(long)(bi + (t >> 6))*DA_ + (t & 63)];
        sk[t >> 6][t & 63] = g_k[(long)(bj + (t >> 6))*DA_ + (t & 63)];
    }
    __syncthreads();
    int ti = tid >> 4, tj = tid & 15;
    float d = 0.f;
#pragma unroll 8
    for (int x = 0; x < DA_; x++) d = fmaf(sq[ti][x], sk[tj][x], d);
    float A = 1.f / (1.f + expf(-d * 0.125f));
    out_av[(long)(bi + ti)*KM + (bj + tj)] = (A > 0.5f) ? A : 0.f;
}

// ---------------- receiver adjacency ----------------
__global__ void arec_kernel(const float* __restrict__ av) {
    long idx = (long)blockIdx.x * 256 + threadIdx.x;
    int i = (int)(idx / KM), j = (int)(idx % KM);
    bool b = (i != j) &&
             (g_adj[(long)j*KM + i] || av[(long)i*KM + j] > 0.f || av[(long)j*KM + i] > 0.f);
    g_arec[idx] = b ? 1 : 0;
}

// ---------------- hn = h_m @ W_node_h ----------------
__global__ __launch_bounds__(128) void gemm_hn_kernel(const float* __restrict__ Wnh) {
    int r0 = blockIdx.x * 8;
    int f = threadIdx.x;
    __shared__ float sA[8][DOUT];
    for (int t = f; t < 8*DOUT; t += 128) {
        int rr = t / DOUT, cc = t % DOUT;
        sA[rr][cc] = g_hm[(long)(r0 + rr)*DOUT + cc];
    }
    __syncthreads();
    float acc[8];
#pragma unroll
    for (int rr = 0; rr < 8; rr++) acc[rr] = 0.f;
    for (int kk = 0; kk < DOUT; kk++) {
        float b = Wnh[kk*FF + f];
#pragma unroll
        for (int rr = 0; rr < 8; rr++) acc[rr] = fmaf(sA[rr][kk], b, acc[rr]);
    }
#pragma unroll
    for (int rr = 0; rr < 8; rr++) g_hn[(long)(r0 + rr)*FF + f] = acc[rr];
}

// ---------------- K x K pair aggregation ----------------
__global__ __launch_bounds__(128) void pair_kernel(const float* __restrict__ Wrh) {
    int i0 = blockIdx.x * 2;
    int f = threadIdx.x;
    __shared__ float sposm[KM*3];
    __shared__ float s_sh[2][128][12];
    __shared__ float s_rad[2][128][8];
    __shared__ unsigned char s_a[2][128];
    for (int t = f; t < KM*3; t += 128) sposm[t] = g_posm[t];
    float wf[8];
#pragma unroll
    for (int rn = 0; rn < 8; rn++) wf[rn] = Wrh[rn*FF + f];
    __syncthreads();
    float pix[2], piy[2], piz[2];
#pragma unroll
    for (int ii = 0; ii < 2; ii++) {
        pix[ii] = sposm[(i0+ii)*3 + 0];
        piy[ii] = sposm[(i0+ii)*3 + 1];
        piz[ii] = sposm[(i0+ii)*3 + 2];
    }
    float acc[2][LL];
#pragma unroll
    for (int ii = 0; ii < 2; ii++)
#pragma unroll
        for (int l = 0; l < LL; l++) acc[ii][l] = 0.f;
    const float cb = sqrtf(2.f / 5.f);

    for (int jb = 0; jb < KM; jb += 128) {
        int j = jb + f;
        float pjx = sposm[j*3], pjy = sposm[j*3+1], pjz = sposm[j*3+2];
#pragma unroll
        for (int ii = 0; ii < 2; ii++) {
            unsigned char a = g_arec[(long)(i0+ii)*KM + j];
            s_a[ii][f] = a;
            if (a) {
                float vx = pjx - pix[ii], vy = pjy - piy[ii], vz = pjz - piz[ii];
                float r = sqrtf(vx*vx + vy*vy + vz*vz);
                float inv = 1.f / fmaxf(r, 1e-9f);
                float ux = vx*inv, uy = vy*inv, uz = vz*inv;
                s_sh[ii][f][0] = 1.f;
                s_sh[ii][f][1] = ux;
                s_sh[ii][f][2] = uy;
                s_sh[ii][f][3] = uz;
                s_sh[ii][f][4] = ux*uy;
                s_sh[ii][f][5] = uy*uz;
                s_sh[ii][f][6] = 3.f*uz*uz - 1.f;
                s_sh[ii][f][7] = ux*uz;
                s_sh[ii][f][8] = ux*ux - uy*uy;
#pragma unroll
                for (int rn = 0; rn < 8; rn++)
                    s_rad[ii][f][rn] = cb * sinf((float)(rn+1) * PI_F * r * 0.2f) * inv;
            }
        }
        __syncthreads();
        for (int jj = 0; jj < 128; jj++) {
            int a0 = s_a[0][jj], a1 = s_a[1][jj];
            if (!(a0 | a1)) continue;
            float hnf = g_hn[(long)(jb + jj)*FF + f];
#pragma unroll
            for (int ii = 0; ii < 2; ii++) {
                if ((ii == 0 && a0) || (ii == 1 && a1)) {
                    float4 r0 = *(const float4*)(&s_rad[ii][jj][0]);
                    float4 r1 = *(const float4*)(&s_rad[ii][jj][4]);
                    float rw = 0.f;
                    rw = fmaf(r0.x, wf[0], rw); rw = fmaf(r0.y, wf[1], rw);
                    rw = fmaf(r0.z, wf[2], rw); rw = fmaf(r0.w, wf[3], rw);
                    rw = fmaf(r1.x, wf[4], rw); rw = fmaf(r1.y, wf[5], rw);
                    rw = fmaf(r1.z, wf[6], rw); rw = fmaf(r1.w, wf[7], rw);
                    float tmv = hnf * rw;
                    float4 s0 = *(const float4*)(&s_sh[ii][jj][0]);
                    float4 s1 = *(const float4*)(&s_sh[ii][jj][4]);
                    float  s8 = s_sh[ii][jj][8];
                    acc[ii][0] = fmaf(s0.x, tmv, acc[ii][0]);
                    acc[ii][1] = fmaf(s0.y, tmv, acc[ii][1]);
                    acc[ii][2] = fmaf(s0.z, tmv, acc[ii][2]);
                    acc[ii][3] = fmaf(s0.w, tmv, acc[ii][3]);
                    acc[ii][4] = fmaf(s1.x, tmv, acc[ii][4]);
                    acc[ii][5] = fmaf(s1.y, tmv, acc[ii][5]);
                    acc[ii][6] = fmaf(s1.z, tmv, acc[ii][6]);
                    acc[ii][7] = fmaf(s1.w, tmv, acc[ii][7]);
                    acc[ii][8] = fmaf(s8,   tmv, acc[ii][8]);
                }
            }
        }
        __syncthreads();
    }
#pragma unroll
    for (int ii = 0; ii < 2; ii++)
#pragma unroll
        for (int l = 0; l < LL; l++)
            g_updm[(long)(i0+ii)*DOUT + l*FF + f] = acc[ii][l];
}

// ---------------- final combine ----------------
__global__ __launch_bounds__(128) void final_kernel(float* __restrict__ out) {
    int n = blockIdx.x;
    int g = blockIdx.y * 128 + threadIdx.x;
    long idx = (long)n*DOUT + g;
    float mm = g_m[n];
    float hl = g_hlocal[idx];
    int rk = g_rank[n];
    float he = (rk < KM) ? g_hhier[(long)rk*DOUT + g] : 0.f;
    out[idx] = (1.f - mm) * hl + mm * he;
}

// ---------------- launcher ----------------
extern "C" void kernel_launch(void* const* d_in, const int* in_sizes, int n_in,
                              void* d_out, int out_size)
{
    const float* h     = (const float*)d_in[0];
    const float* pos   = (const float*)d_in[1];
    const float* esh   = (const float*)d_in[2];
    const float* efeat = (const float*)d_in[3];
    const float* Wnl   = (const float*)d_in[4];
    const float* Wrl   = (const float*)d_in[5];
    const float* Wpl   = (const float*)d_in[6];
    const float* W1    = (const float*)d_in[7];
    const float* b1    = (const float*)d_in[8];
    const float* W2    = (const float*)d_in[9];
    const float* b2    = (const float*)d_in[10];
    const float* Wq    = (const float*)d_in[11];
    const float* Wk    = (const float*)d_in[12];
    const float* Wnh   = (const float*)d_in[13];
    const float* Wrh   = (const float*)d_in[14];
    const float* Wph   = (const float*)d_in[15];
    const int*   eidx  = (const int*)d_in[16];
    float* out = (float*)d_out;

    const size_t OFF_AV = (size_t)NN * DOUT;
    const size_t OFF_M  = OFF_AV + (size_t)KM * KM;
    const size_t OFF_MI = OFF_M + (size_t)NN;

    void *p_hW=0, *p_upd=0, *p_hlocal=0, *p_updm=0, *p_hhier=0;
    void *pA0=0,*pA1=0,*pAm0=0,*pAm1=0;
    void *pBL0=0,*pBL1=0,*pBH0=0,*pBH1=0;
    cudaGetSymbolAddress(&p_hW, g_hW);
    cudaGetSymbolAddress(&p_upd, g_upd);
    cudaGetSymbolAddress(&p_hlocal, g_hlocal);
    cudaGetSymbolAddress(&p_updm, g_updm);
    cudaGetSymbolAddress(&p_hhier, g_hhier);
    cudaGetSymbolAddress(&pA0, g_A0);   cudaGetSymbolAddress(&pA1, g_A1);
    cudaGetSymbolAddress(&pAm0, g_Am0); cudaGetSymbolAddress(&pAm1, g_Am1);
    cudaGetSymbolAddress(&pBL0, g_BL0); cudaGetSymbolAddress(&pBL1, g_BL1);
    cudaGetSymbolAddress(&pBH0, g_BH0); cudaGetSymbolAddress(&pBH1, g_BH1);

    cudaFuncSetAttribute(mma_gemm, cudaFuncAttributeMaxDynamicSharedMemorySize, GSME);

    // 0) zero scratch
    zero_kernel<<<4608, 256>>>();

    // 1) hW = h @ W_node_l (exact fp32)
    sgemm2<<<dim3(1, 128, 1), 256>>>(h, Wnl, (float*)p_hW, NN, FF, FF);

    // 2) CSR build
    count_kernel<<<E_/256, 256>>>(eidx);
    scan_counts<<<1, 1024>>>();
    scatter_kernel<<<E_/256, 256>>>(eidx);

    // weight splits (independent; issue early)
    splitWT2_kernel<<<(DOUT*DOUT + 255)/256, 256>>>(Wpl, (__nv_bfloat16*)pBL0, (__nv_bfloat16*)pBL1);
    splitWT2_kernel<<<(DOUT*DOUT + 255)/256, 256>>>(Wph, (__nv_bfloat16*)pBH0, (__nv_bfloat16*)pBH1);

    // 3) message aggregation -> g_upd
    upd_kernel<<<NN, 128>>>(esh, efeat, Wrl, eidx);

    // 4) h_local: cols 0-127 EXACT fp32 (threshold-critical: m, top-K, q/k);
    //    cols 128-1151 via bf16x2 HMMA (3 products). Then += pad(h).
    sgemm2<<<dim3(1, NN/128, 1), 256>>>((const float*)p_upd, Wpl,
                                        (float*)p_hlocal, NN, DOUT, DOUT);
    split2_kernel<<<(int)(((long)NN*DOUT + 255)/256), 256>>>((const float*)p_upd,
        (__nv_bfloat16*)pA0, (__nv_bfloat16*)pA1, (long)NN*DOUT);
    mma_gemm<<<dim3((DOUT-FF)/128, NN/128, 1), 256, GSME>>>(
        (const __nv_bfloat16*)pA0, (const __nv_bfloat16*)pA1,
        (const __nv_bfloat16*)pBL0, (const __nv_bfloat16*)pBL1,
        (float*)p_hlocal, DOUT/16, FF);
    add_h_kernel<<<NN, 128>>>(h);

    // 5) mask MLP (exact)
    mlp_kernel<<<NN, 64>>>(W1, b1, W2, b2, out + OFF_M);

    // 6) exact top-K
    rank_count_kernel<<<dim3(NN/256, 16), 256>>>();
    mark_master_kernel<<<NN/256, 256>>>();
    scan_master<<<1, 1024>>>(out + OFF_MI);

    // 7) adjacency + gathers
    adj_kernel<<<E_/256, 256>>>(eidx);
    gather_hm_kernel<<<dim3(KM, DOUT/128), 128>>>();
    gather_posm_kernel<<<(KM*3 + 255)/256, 256>>>(pos);

    // 8) virtual attention (exact)
    qk_kernel<<<KM, 64>>>(Wq, Wk);
    attn_kernel<<<dim3(KM/16, KM/16), 256>>>(out + OFF_AV);
    arec_kernel<<<(KM*KM)/256, 256>>>(out + OFF_AV);

    // 9) hierarchical update
    gemm_hn_kernel<<<KM/8, 128>>>(Wnh);
    pair_kernel<<<KM/2, 128>>>(Wrh);

    // 10) h_hier = upd_m @ W_prod_h (bf16x2 HMMA, split-K=4 atomic) + h_m
    split2_kernel<<<(int)(((long)KM*DOUT + 255)/256), 256>>>((const float*)p_updm,
        (__nv_bfloat16*)pAm0, (__nv_bfloat16*)pAm1, (long)KM*DOUT);
    mma_gemm<<<dim3(DOUT/128, KM/128, 4), 256, GSME>>>(
        (const __nv_bfloat16*)pAm0, (const __nv_bfloat16*)pAm1,
        (const __nv_bfloat16*)pBH0, (const __nv_bfloat16*)pBH1,
        (float*)p_hhier, (DOUT/16)/4, 0);
    add_hm_kernel<<<dim3(KM, DOUT/128), 128>>>();

    // 11) combine
    final_kernel<<<dim3(NN, DOUT/128), 128>>>(out);
}